// round 1
// baseline (speedup 1.0000x reference)
#include <cuda_runtime.h>

#define NN 100000
#define EE 400000
#define GG 256
#define HH 256
#define BIOD 512
#define GEPS 1e-5f

// ---------------- scratch (device globals; no allocation in kernel_launch) -----
static __device__ float d_h[(size_t)NN * HH];
static __device__ float d_z[(size_t)NN * HH];
static __device__ float d_t[(size_t)NN * HH];
static __device__ float d_e[(size_t)EE * HH];
static __device__ float d_et[(size_t)EE * HH];
static __device__ float d_scale[EE];
static __device__ int   d_deg[NN];
static __device__ int   d_rowptr[NN + 1];
static __device__ int   d_cursor[NN];
static __device__ int   d_csr[EE];
static __device__ float d_Wc[4 * HH];
static __device__ float d_bc[HH];
static __device__ float d_biob[HH];
static __device__ float d_gsum[GG * HH];
static __device__ float d_gvar[GG * HH];
static __device__ float d_gmean[GG * HH];
static __device__ float d_gcnt[GG];
static __device__ float d_gpool[GG * HH];

// ---------------- small helpers ----------------
__global__ void k_zero_f(float* p, int n) {
    int i = blockIdx.x * blockDim.x + threadIdx.x;
    if (i < n) p[i] = 0.f;
}
__global__ void k_zero_i(int* p, int n) {
    int i = blockIdx.x * blockDim.x + threadIdx.x;
    if (i < n) p[i] = 0;
}

// Fold edge_emb + edge_mlp layer1 into a 4x256 weight; fold mean_bio into head bias.
__global__ void k_prep(const float* __restrict__ Wemb, const float* __restrict__ eb,
                       const float* __restrict__ W1, const float* __restrict__ b1,
                       const float* __restrict__ bio, const float* __restrict__ hW1,
                       const float* __restrict__ hb1) {
    int j = threadIdx.x;  // 256 threads
    float wc0 = 0.f, wc1 = 0.f, wc2 = 0.f, wc3 = 0.f, bc = 0.f;
    for (int d = 0; d < HH; d++) {
        float w = W1[d * HH + j];
        wc0 += Wemb[0 * HH + d] * w;
        wc1 += Wemb[1 * HH + d] * w;
        wc2 += Wemb[2 * HH + d] * w;
        wc3 += Wemb[3 * HH + d] * w;
        bc  += eb[d] * w;
    }
    d_Wc[0 * HH + j] = wc0;
    d_Wc[1 * HH + j] = wc1;
    d_Wc[2 * HH + j] = wc2;
    d_Wc[3 * HH + j] = wc3;
    d_bc[j] = bc + b1[j];
    float bb = hb1[j];
    for (int k = 0; k < BIOD; k++) bb += bio[k] * hW1[(HH + k) * HH + j];
    d_biob[j] = bb;
}

// h[n] = node_emb_W[x[n]]
__global__ void k_node_emb(const int* __restrict__ x, const float* __restrict__ emb) {
    int idx = blockIdx.x * blockDim.x + threadIdx.x;  // over NN*64 float4 slots
    int node = idx >> 6;
    int q = idx & 63;
    if (node >= NN) return;
    int xv = x[node];
    float4 v = *(const float4*)(emb + (size_t)xv * HH + q * 4);
    *(float4*)(d_h + (size_t)node * HH + q * 4) = v;
}

// t_e = relu(attr @ Wc + bc); scale[e] = attr[1] > 0 ? struct_scale : 1
__global__ void k_edge_pre(const float* __restrict__ attr, const float* __restrict__ sscale) {
    __shared__ float sWc[4 * HH];
    int tid = threadIdx.x;  // 256
    ((float4*)sWc)[tid] = ((const float4*)d_Wc)[tid];
    __syncthreads();
    int e = blockIdx.x * 4 + (tid >> 6);
    int q = tid & 63;
    if (e >= EE) return;
    float a0 = __ldg(attr + (size_t)e * 4 + 0);
    float a1 = __ldg(attr + (size_t)e * 4 + 1);
    float a2 = __ldg(attr + (size_t)e * 4 + 2);
    float a3 = __ldg(attr + (size_t)e * 4 + 3);
    float4 b  = *(const float4*)(d_bc + q * 4);
    float4 w0 = *(const float4*)(sWc + 0 * HH + q * 4);
    float4 w1 = *(const float4*)(sWc + 1 * HH + q * 4);
    float4 w2 = *(const float4*)(sWc + 2 * HH + q * 4);
    float4 w3 = *(const float4*)(sWc + 3 * HH + q * 4);
    float4 o;
    o.x = fmaxf(a0 * w0.x + a1 * w1.x + a2 * w2.x + a3 * w3.x + b.x, 0.f);
    o.y = fmaxf(a0 * w0.y + a1 * w1.y + a2 * w2.y + a3 * w3.y + b.y, 0.f);
    o.z = fmaxf(a0 * w0.z + a1 * w1.z + a2 * w2.z + a3 * w3.z + b.z, 0.f);
    o.w = fmaxf(a0 * w0.w + a1 * w1.w + a2 * w2.w + a3 * w3.w + b.w, 0.f);
    *(float4*)(d_et + (size_t)e * HH + q * 4) = o;
    if (q == 0) d_scale[e] = (a1 > 0.f) ? *sscale : 1.f;
}

// ---------------- fp32 tiled GEMM: C[M,256] = op(A[M,256] @ W[256,256] + bias) ----
template <bool RELU, bool SCALE>
__global__ __launch_bounds__(256) void k_gemm256(
    const float* __restrict__ A, const float* __restrict__ W,
    const float* __restrict__ bias, const float* __restrict__ rowscale,
    float* __restrict__ C, int M) {
    constexpr int BM = 128, BN = 64, BK = 16;
    __shared__ float As[BK][BM + 4];
    __shared__ float Ws[BK][BN];
    int row0 = blockIdx.x * BM;
    int col0 = blockIdx.y * BN;
    int tid = threadIdx.x;
    int ty = tid >> 4, tx = tid & 15;  // ty:16 row-groups of 8, tx:16 col-groups of 4
    float acc[8][4];
#pragma unroll
    for (int i = 0; i < 8; i++)
#pragma unroll
        for (int j = 0; j < 4; j++) acc[i][j] = 0.f;

    for (int k0 = 0; k0 < HH; k0 += BK) {
#pragma unroll
        for (int it = 0; it < 2; it++) {
            int id = tid + it * 256;       // float4 id within 128x16 tile
            int r = id >> 2;
            int c4 = (id & 3) * 4;
            float4 v = make_float4(0.f, 0.f, 0.f, 0.f);
            if (row0 + r < M)
                v = *(const float4*)(A + (size_t)(row0 + r) * HH + k0 + c4);
            As[c4 + 0][r] = v.x;
            As[c4 + 1][r] = v.y;
            As[c4 + 2][r] = v.z;
            As[c4 + 3][r] = v.w;
        }
        {
            int r = tid >> 4;
            int c4 = (tid & 15) * 4;
            float4 v = *(const float4*)(W + (size_t)(k0 + r) * HH + col0 + c4);
            *(float4*)&Ws[r][c4] = v;
        }
        __syncthreads();
#pragma unroll
        for (int k = 0; k < BK; k++) {
            float a[8], b[4];
            *(float4*)&a[0] = *(const float4*)&As[k][ty * 8];
            *(float4*)&a[4] = *(const float4*)&As[k][ty * 8 + 4];
            *(float4*)&b[0] = *(const float4*)&Ws[k][tx * 4];
#pragma unroll
            for (int i = 0; i < 8; i++)
#pragma unroll
                for (int j = 0; j < 4; j++) acc[i][j] += a[i] * b[j];
        }
        __syncthreads();
    }
    float bv[4];
    *(float4*)bv = *(const float4*)(bias + col0 + tx * 4);
#pragma unroll
    for (int i = 0; i < 8; i++) {
        int r = row0 + ty * 8 + i;
        if (r >= M) continue;
        float v0 = acc[i][0] + bv[0];
        float v1 = acc[i][1] + bv[1];
        float v2 = acc[i][2] + bv[2];
        float v3 = acc[i][3] + bv[3];
        if (RELU) {
            v0 = fmaxf(v0, 0.f); v1 = fmaxf(v1, 0.f);
            v2 = fmaxf(v2, 0.f); v3 = fmaxf(v3, 0.f);
        }
        if (SCALE) {
            float s = rowscale[r];
            v0 *= s; v1 *= s; v2 *= s; v3 *= s;
        }
        *(float4*)(C + (size_t)r * HH + col0 + tx * 4) = make_float4(v0, v1, v2, v3);
    }
}

// ---------------- CSR build over dst ----------------
__global__ void k_deg(const int* __restrict__ ei) {
    int e = blockIdx.x * blockDim.x + threadIdx.x;
    if (e < EE) atomicAdd(&d_deg[ei[EE + e]], 1);
}
__global__ void k_scan() {
    __shared__ int s[1024];
    int tid = threadIdx.x;
    const int chunk = (NN + 1023) / 1024;
    int beg = tid * chunk;
    int end = min(beg + chunk, NN);
    int sum = 0;
    for (int i = beg; i < end; i++) sum += d_deg[i];
    s[tid] = sum;
    __syncthreads();
    for (int off = 1; off < 1024; off <<= 1) {
        int v = (tid >= off) ? s[tid - off] : 0;
        __syncthreads();
        s[tid] += v;
        __syncthreads();
    }
    int run = (tid > 0) ? s[tid - 1] : 0;
    for (int i = beg; i < end; i++) {
        d_rowptr[i] = run;
        run += d_deg[i];
    }
    if (tid == 1023) d_rowptr[NN] = s[1023];
}
__global__ void k_cursor() {
    int i = blockIdx.x * blockDim.x + threadIdx.x;
    if (i < NN) d_cursor[i] = d_rowptr[i];
}
__global__ void k_fill(const int* __restrict__ ei) {
    int e = blockIdx.x * blockDim.x + threadIdx.x;
    if (e < EE) {
        int dst = ei[EE + e];
        int p = atomicAdd(&d_cursor[dst], 1);
        d_csr[p] = e;
    }
}
__global__ void k_cnt(const int* __restrict__ batch) {
    int i = blockIdx.x * blockDim.x + threadIdx.x;
    if (i < NN) atomicAdd(&d_gcnt[batch[i]], 1.f);
}

// z = (1+eps_l)*h + sum_{e in csr(node)} relu(h[src[e]] + e[e])
__global__ void k_aggregate(const int* __restrict__ ei, const float* __restrict__ conv_eps, int l) {
    int tid = threadIdx.x;
    int node = blockIdx.x * 4 + (tid >> 6);
    int q = tid & 63;
    if (node >= NN) return;
    float eps1 = 1.f + conv_eps[l];
    float4 acc = make_float4(0.f, 0.f, 0.f, 0.f);
    int pbeg = d_rowptr[node];
    int pend = d_rowptr[node + 1];
    for (int p = pbeg; p < pend; p++) {
        int eid = d_csr[p];
        int src = ei[eid];
        float4 hv = *(const float4*)(d_h + (size_t)src * HH + q * 4);
        float4 ev = *(const float4*)(d_e + (size_t)eid * HH + q * 4);
        acc.x += fmaxf(hv.x + ev.x, 0.f);
        acc.y += fmaxf(hv.y + ev.y, 0.f);
        acc.z += fmaxf(hv.z + ev.z, 0.f);
        acc.w += fmaxf(hv.w + ev.w, 0.f);
    }
    float4 hq = *(const float4*)(d_h + (size_t)node * HH + q * 4);
    float4 z;
    z.x = eps1 * hq.x + acc.x;
    z.y = eps1 * hq.y + acc.y;
    z.z = eps1 * hq.z + acc.z;
    z.w = eps1 * hq.w + acc.w;
    *(float4*)(d_z + (size_t)node * HH + q * 4) = z;
}

// chunked (sorted-batch) segment sum: out[g][d] += sum over node runs
__global__ void k_seg_sum(const float* __restrict__ src, float* __restrict__ out,
                          const int* __restrict__ batch) {
    int n0 = blockIdx.x * 16;
    int d = threadIdx.x;
    float acc = 0.f;
    int cur = -1;
#pragma unroll 4
    for (int i = 0; i < 16; i++) {
        int node = n0 + i;
        if (node >= NN) break;
        int g = batch[node];
        if (g != cur) {
            if (cur >= 0) atomicAdd(&out[cur * HH + d], acc);
            cur = g;
            acc = 0.f;
        }
        acc += src[(size_t)node * HH + d];
    }
    if (cur >= 0) atomicAdd(&out[cur * HH + d], acc);
}

__global__ void k_seg_var(const int* __restrict__ batch, const float* __restrict__ alpha_l) {
    int n0 = blockIdx.x * 16;
    int d = threadIdx.x;
    float a = alpha_l[d];
    float acc = 0.f, m = 0.f;
    int cur = -1;
#pragma unroll 4
    for (int i = 0; i < 16; i++) {
        int node = n0 + i;
        if (node >= NN) break;
        int g = batch[node];
        if (g != cur) {
            if (cur >= 0) atomicAdd(&d_gvar[cur * HH + d], acc);
            cur = g;
            acc = 0.f;
            m = d_gmean[g * HH + d];
        }
        float hc = d_h[(size_t)node * HH + d] - a * m;
        acc += hc * hc;
    }
    if (cur >= 0) atomicAdd(&d_gvar[cur * HH + d], acc);
}

// dst[i] = src[i] / max(cnt[graph],1)
__global__ void k_fin(float* __restrict__ dst, const float* __restrict__ src, int n) {
    int i = blockIdx.x * blockDim.x + threadIdx.x;
    if (i < n) {
        float c = d_gcnt[i >> 8];
        dst[i] = src[i] / fmaxf(c, 1.f);
    }
}

// h = gamma*(h - alpha*mean)*rsqrt(var+eps) + beta
__global__ void k_norm(const int* __restrict__ batch, const float* __restrict__ gamma,
                       const float* __restrict__ beta, const float* __restrict__ alpha, int l) {
    int idx = blockIdx.x * blockDim.x + threadIdx.x;
    int node = idx >> 6;
    int q = idx & 63;
    if (node >= NN) return;
    int g = batch[node];
    float4 h = *(const float4*)(d_h + (size_t)node * HH + q * 4);
    float4 m = *(const float4*)(d_gmean + g * HH + q * 4);
    float4 v = *(const float4*)(d_gvar + g * HH + q * 4);
    float4 ga = *(const float4*)(gamma + l * HH + q * 4);
    float4 be = *(const float4*)(beta + l * HH + q * 4);
    float4 al = *(const float4*)(alpha + l * HH + q * 4);
    h.x = ga.x * (h.x - al.x * m.x) * rsqrtf(v.x + GEPS) + be.x;
    h.y = ga.y * (h.y - al.y * m.y) * rsqrtf(v.y + GEPS) + be.y;
    h.z = ga.z * (h.z - al.z * m.z) * rsqrtf(v.z + GEPS) + be.z;
    h.w = ga.w * (h.w - al.w * m.w) * rsqrtf(v.w + GEPS) + be.w;
    *(float4*)(d_h + (size_t)node * HH + q * 4) = h;
}

// head: out[g] = relu(gpool[g] @ W1[:256] + biob) @ W2 + b2
__global__ void k_head(const float* __restrict__ hW1, const float* __restrict__ hW2,
                       const float* __restrict__ hb2, float* __restrict__ out) {
    int g = blockIdx.x;
    int j = threadIdx.x;
    __shared__ float red[256];
    float acc = d_biob[j];
    const float* grow = d_gpool + g * HH;
    for (int k = 0; k < HH; k++) acc += grow[k] * hW1[k * HH + j];
    red[j] = fmaxf(acc, 0.f) * hW2[j];
    __syncthreads();
    for (int off = 128; off > 0; off >>= 1) {
        if (j < off) red[j] += red[j + off];
        __syncthreads();
    }
    if (j == 0) out[g] = red[0] + hb2[0];
}

// ---------------- launch ----------------
extern "C" void kernel_launch(void* const* d_in, const int* in_sizes, int n_in,
                              void* d_out, int out_size) {
    const int* x = (const int*)d_in[0];
    const int* ei = (const int*)d_in[1];
    const float* edge_attr = (const float*)d_in[2];
    const int* batch = (const int*)d_in[3];
    const float* node_emb_W = (const float*)d_in[4];
    const float* edge_emb_W = (const float*)d_in[5];
    const float* edge_emb_b = (const float*)d_in[6];
    const float* edge_mlp_W1 = (const float*)d_in[7];
    const float* edge_mlp_b1 = (const float*)d_in[8];
    const float* edge_mlp_W2 = (const float*)d_in[9];
    const float* edge_mlp_b2 = (const float*)d_in[10];
    const float* struct_scale = (const float*)d_in[11];
    const float* conv_W1 = (const float*)d_in[12];
    const float* conv_b1 = (const float*)d_in[13];
    const float* conv_W2 = (const float*)d_in[14];
    const float* conv_b2 = (const float*)d_in[15];
    const float* conv_eps = (const float*)d_in[16];
    const float* norm_gamma = (const float*)d_in[17];
    const float* norm_beta = (const float*)d_in[18];
    const float* norm_alpha = (const float*)d_in[19];
    const float* mean_bio = (const float*)d_in[20];
    const float* head_W1 = (const float*)d_in[21];
    const float* head_b1 = (const float*)d_in[22];
    const float* head_W2 = (const float*)d_in[23];
    const float* head_b2 = (const float*)d_in[24];
    float* out = (float*)d_out;

    float* p_deg_f;  // unused; addresses of globals fetched via symbols below
    (void)p_deg_f; (void)in_sizes; (void)n_in; (void)out_size;

    // globals are accessed directly inside kernels except where passed:
    float *g_gsum, *g_gvar, *g_gmean, *g_gcnt, *g_gpool, *g_et, *g_e, *g_scale, *g_z, *g_t, *g_h;
    int* g_deg;
    cudaGetSymbolAddress((void**)&g_gsum, d_gsum);
    cudaGetSymbolAddress((void**)&g_gvar, d_gvar);
    cudaGetSymbolAddress((void**)&g_gmean, d_gmean);
    cudaGetSymbolAddress((void**)&g_gcnt, d_gcnt);
    cudaGetSymbolAddress((void**)&g_gpool, d_gpool);
    cudaGetSymbolAddress((void**)&g_et, d_et);
    cudaGetSymbolAddress((void**)&g_e, d_e);
    cudaGetSymbolAddress((void**)&g_scale, d_scale);
    cudaGetSymbolAddress((void**)&g_z, d_z);
    cudaGetSymbolAddress((void**)&g_t, d_t);
    cudaGetSymbolAddress((void**)&g_h, d_h);
    cudaGetSymbolAddress((void**)&g_deg, d_deg);

    // 1. fold small weights
    k_prep<<<1, 256>>>(edge_emb_W, edge_emb_b, edge_mlp_W1, edge_mlp_b1,
                       mean_bio, head_W1, head_b1);
    // 2. node embedding
    k_node_emb<<<(NN * 64 + 255) / 256, 256>>>(x, node_emb_W);
    // 3. edge pre: t = relu(attr@Wc + bc), scale
    k_edge_pre<<<(EE + 3) / 4, 256>>>(edge_attr, struct_scale);
    // 4. e = (t @ W2 + b2) * scale   [400000 x 256 x 256]
    k_gemm256<false, true><<<dim3(EE / 128, 4), 256>>>(g_et, edge_mlp_W2, edge_mlp_b2,
                                                       g_scale, g_e, EE);
    // 5. CSR build
    k_zero_i<<<(NN + 255) / 256, 256>>>(g_deg, NN);
    k_deg<<<(EE + 255) / 256, 256>>>(ei);
    k_scan<<<1, 1024>>>();
    k_cursor<<<(NN + 255) / 256, 256>>>();
    k_fill<<<(EE + 255) / 256, 256>>>(ei);
    // 6. per-graph counts (once)
    k_zero_f<<<1, 256>>>(g_gcnt, GG);
    k_cnt<<<(NN + 255) / 256, 256>>>(batch);

    const int gemmM_blocks = (NN + 127) / 128;
    for (int l = 0; l < 3; l++) {
        k_aggregate<<<(NN + 3) / 4, 256>>>(ei, conv_eps, l);
        k_gemm256<true, false><<<dim3(gemmM_blocks, 4), 256>>>(
            g_z, conv_W1 + (size_t)l * HH * HH, conv_b1 + l * HH, nullptr, g_t, NN);
        k_gemm256<false, false><<<dim3(gemmM_blocks, 4), 256>>>(
            g_t, conv_W2 + (size_t)l * HH * HH, conv_b2 + l * HH, nullptr, g_h, NN);
        // GraphNorm
        k_zero_f<<<(GG * HH + 255) / 256, 256>>>(g_gsum, GG * HH);
        k_seg_sum<<<(NN + 15) / 16, 256>>>(g_h, g_gsum, batch);
        k_fin<<<(GG * HH + 255) / 256, 256>>>(g_gmean, g_gsum, GG * HH);
        k_zero_f<<<(GG * HH + 255) / 256, 256>>>(g_gvar, GG * HH);
        k_seg_var<<<(NN + 15) / 16, 256>>>(batch, norm_alpha + l * HH);
        k_fin<<<(GG * HH + 255) / 256, 256>>>(g_gvar, g_gvar, GG * HH);
        k_norm<<<(NN * 64 + 255) / 256, 256>>>(batch, norm_gamma, norm_beta, norm_alpha, l);
    }

    // 7. mean pool
    k_zero_f<<<(GG * HH + 255) / 256, 256>>>(g_gsum, GG * HH);
    k_seg_sum<<<(NN + 15) / 16, 256>>>(g_h, g_gsum, batch);
    k_fin<<<(GG * HH + 255) / 256, 256>>>(g_gpool, g_gsum, GG * HH);
    // 8. head
    k_head<<<GG, 256>>>(head_W1, head_W2, head_b2, out);
}

// round 3
// speedup vs baseline: 1.4103x; 1.4103x over previous
#include <cuda_runtime.h>
#include <cuda_bf16.h>
#include <cstdint>

#define NN 100000
#define EE 400000
#define GG 256
#define HH 256
#define BIOD 512
#define GEPS 1e-5f

// ---------------- scratch (device globals; no allocation in kernel_launch) -----
static __device__ float d_h[(size_t)NN * HH];
static __device__ float d_z[(size_t)NN * HH];
static __device__ float d_t[(size_t)NN * HH];
static __device__ float d_e[(size_t)EE * HH];
static __device__ int   d_deg[NN];
static __device__ int   d_rowptr[NN + 1];
static __device__ int   d_cursor[NN];
static __device__ int   d_csr[EE];
static __device__ float d_Wc[4 * HH];
static __device__ float d_bc[HH];
static __device__ float d_biob[HH];
static __device__ float d_gsum[GG * HH];
static __device__ float d_gvar[GG * HH];
static __device__ float d_gmean[GG * HH];
static __device__ float d_gcnt[GG];
static __device__ float d_gpool[GG * HH];
// 7 weight matrices x (hi, lo) x 256x256 bf16, layout [mat][hi/lo][n][k]
static __device__ unsigned short d_wsplit[(size_t)7 * 2 * 65536];

// ---------------- mma helpers ----------------
__device__ __forceinline__ uint32_t smem_to_u32(const void* smem_ptr) {
    uint32_t addr;
    asm("{ .reg .u64 tmp; cvta.to.shared.u64 tmp, %1; cvt.u32.u64 %0, tmp; }"
        : "=r"(addr) : "l"(smem_ptr));
    return addr;
}
__device__ __forceinline__ void ldsm4(unsigned* r, uint32_t addr) {
    asm volatile("ldmatrix.sync.aligned.m8n8.x4.shared.b16 {%0,%1,%2,%3}, [%4];"
                 : "=r"(r[0]), "=r"(r[1]), "=r"(r[2]), "=r"(r[3]) : "r"(addr));
}
__device__ __forceinline__ void ldsm2(unsigned* r, uint32_t addr) {
    asm volatile("ldmatrix.sync.aligned.m8n8.x2.shared.b16 {%0,%1}, [%2];"
                 : "=r"(r[0]), "=r"(r[1]) : "r"(addr));
}
__device__ __forceinline__ void mma16816(float* d, const unsigned* a, const unsigned* b) {
    asm volatile(
        "mma.sync.aligned.m16n8k16.row.col.f32.bf16.bf16.f32 "
        "{%0,%1,%2,%3}, {%4,%5,%6,%7}, {%8,%9}, {%0,%1,%2,%3};"
        : "+f"(d[0]), "+f"(d[1]), "+f"(d[2]), "+f"(d[3])
        : "r"(a[0]), "r"(a[1]), "r"(a[2]), "r"(a[3]), "r"(b[0]), "r"(b[1]));
}

// hi/lo bf16 split of two floats, packed as bf16x2 words
__device__ __forceinline__ unsigned packhl(float a, float b, unsigned& lo_out) {
    __nv_bfloat16 ha = __float2bfloat16_rn(a), hb = __float2bfloat16_rn(b);
    float ra = a - __bfloat162float(ha), rb = b - __bfloat162float(hb);
    __nv_bfloat16 la = __float2bfloat16_rn(ra), lb = __float2bfloat16_rn(rb);
    lo_out = (unsigned)__bfloat16_as_ushort(la) | ((unsigned)__bfloat16_as_ushort(lb) << 16);
    return (unsigned)__bfloat16_as_ushort(ha) | ((unsigned)__bfloat16_as_ushort(hb) << 16);
}

// ============================================================================
// bf16x3-split tensor-core GEMM:  C[M,256] = op(A[M,256] @ W[256,256] + bias)
// AF: A computed on the fly as relu(attr@Wc+bc) (edge MLP layer-1 fused)
// RELU: relu epilogue; SC: per-row struct-scale from attr[:,1].
// Block 128x128, BK=64, 8 warps (4m x 2n), warp tile 32x64.
// ============================================================================
#define PITCH 72
#define SMEM_BYTES (4 * 128 * PITCH * 2)   // 73728

template <bool AF, bool RELU, bool SC>
__global__ __launch_bounds__(256, 2) void k_mma(
    const float* __restrict__ A, const float* __restrict__ attr,
    const unsigned short* __restrict__ Wsp,  // [hi 65536][lo 65536], [n][k]
    const float* __restrict__ bias, const float* __restrict__ sscale,
    float* __restrict__ C, int M) {
    extern __shared__ __nv_bfloat16 smbf[];
    __nv_bfloat16* sAhi = smbf;                     // elem offsets
    __nv_bfloat16* sAlo = smbf + 9216;
    __nv_bfloat16* sBhi = smbf + 18432;
    __nv_bfloat16* sBlo = smbf + 27648;
    const uint32_t sbase = smem_to_u32(smbf);

    int tid = threadIdx.x;
    int lane = tid & 31, wid = tid >> 5;
    int wm = wid & 3, wn = wid >> 2;
    int row0 = blockIdx.x * 128;
    int n0 = blockIdx.y * 128;
    const unsigned short* Whi = Wsp;
    const unsigned short* Wlo = Wsp + 65536;

    float acc[2][8][4];
#pragma unroll
    for (int mt = 0; mt < 2; mt++)
#pragma unroll
        for (int nt = 0; nt < 8; nt++)
#pragma unroll
            for (int j = 0; j < 4; j++) acc[mt][nt][j] = 0.f;

    for (int c = 0; c < 4; c++) {
        int k0 = c * 64;
        // ---- stage B chunk [128 n][64 k] hi+lo ----
        {
            int n = tid >> 1, kh = (tid & 1) * 32;
            const unsigned short* ph = Whi + (size_t)(n0 + n) * 256 + k0 + kh;
            const unsigned short* pl = Wlo + (size_t)(n0 + n) * 256 + k0 + kh;
#pragma unroll
            for (int j = 0; j < 4; j++) {
                uint4 vh = *(const uint4*)(ph + j * 8);
                uint4 vl = *(const uint4*)(pl + j * 8);
                *(uint4*)&sBhi[n * PITCH + kh + j * 8] = vh;
                *(uint4*)&sBlo[n * PITCH + kh + j * 8] = vl;
            }
        }
        // ---- stage A chunk [128 m][64 k] hi+lo ----
        {
            int r = tid >> 1, kh = (tid & 1) * 32;
            if (AF) {
                float4 a = *(const float4*)(attr + (size_t)(row0 + r) * 4);
#pragma unroll
                for (int j = 0; j < 16; j++) {
                    int k = k0 + kh + 2 * j;
                    float v0 = fmaxf(a.x * d_Wc[k] + a.y * d_Wc[256 + k] +
                                     a.z * d_Wc[512 + k] + a.w * d_Wc[768 + k] + d_bc[k], 0.f);
                    float v1 = fmaxf(a.x * d_Wc[k + 1] + a.y * d_Wc[257 + k] +
                                     a.z * d_Wc[513 + k] + a.w * d_Wc[769 + k] + d_bc[k + 1], 0.f);
                    unsigned lo, hi = packhl(v0, v1, lo);
                    *(unsigned*)&sAhi[r * PITCH + kh + 2 * j] = hi;
                    *(unsigned*)&sAlo[r * PITCH + kh + 2 * j] = lo;
                }
            } else {
                bool ok = (row0 + r) < M;
                const float* Ar = A + (size_t)(row0 + r) * HH + k0 + kh;
#pragma unroll
                for (int q = 0; q < 8; q++) {
                    float4 v = ok ? *(const float4*)(Ar + q * 4) : make_float4(0.f, 0.f, 0.f, 0.f);
                    uint2 hi, lo;
                    hi.x = packhl(v.x, v.y, lo.x);
                    hi.y = packhl(v.z, v.w, lo.y);
                    *(uint2*)&sAhi[r * PITCH + kh + q * 4] = hi;
                    *(uint2*)&sAlo[r * PITCH + kh + q * 4] = lo;
                }
            }
        }
        __syncthreads();

        // ---- compute: 4 k16-steps; 3 split-products each ----
#pragma unroll
        for (int ks = 0; ks < 64; ks += 16) {
            unsigned fAh[2][4], fAl[2][4];
#pragma unroll
            for (int mt = 0; mt < 2; mt++) {
                int mrow = wm * 32 + mt * 16 + (lane & 15);
                uint32_t off = (uint32_t)(mrow * PITCH + ks + ((lane >> 4) << 3)) * 2;
                ldsm4(fAh[mt], sbase + off);
                ldsm4(fAl[mt], sbase + 18432 + off);
            }
#pragma unroll
            for (int nt = 0; nt < 8; nt++) {
                int l = lane & 15;
                int nrow = wn * 64 + nt * 8 + (l & 7);
                uint32_t off = (uint32_t)(nrow * PITCH + ks + ((l & 8) ? 8 : 0)) * 2;
                unsigned fBh[2], fBl[2];
                ldsm2(fBh, sbase + 36864 + off);
                ldsm2(fBl, sbase + 55296 + off);
#pragma unroll
                for (int mt = 0; mt < 2; mt++) {
                    mma16816(acc[mt][nt], fAh[mt], fBh);
                    mma16816(acc[mt][nt], fAh[mt], fBl);
                    mma16816(acc[mt][nt], fAl[mt], fBh);
                }
            }
        }
        __syncthreads();
    }

    // ---- epilogue: bias / relu / struct-scale, direct coalesced-ish stores ----
#pragma unroll
    for (int mt = 0; mt < 2; mt++) {
        int r1 = row0 + wm * 32 + mt * 16 + (lane >> 2);
        int r2 = r1 + 8;
        float s1 = 1.f, s2 = 1.f;
        if (SC) {
            float ssv = __ldg(sscale);
            s1 = (attr[(size_t)r1 * 4 + 1] > 0.f) ? ssv : 1.f;
            s2 = (attr[(size_t)r2 * 4 + 1] > 0.f) ? ssv : 1.f;
        }
#pragma unroll
        for (int nt = 0; nt < 8; nt++) {
            int col = n0 + wn * 64 + nt * 8 + 2 * (lane & 3);
            float2 b = *(const float2*)(bias + col);
            float v0 = acc[mt][nt][0] + b.x, v1 = acc[mt][nt][1] + b.y;
            float v2 = acc[mt][nt][2] + b.x, v3 = acc[mt][nt][3] + b.y;
            if (RELU) {
                v0 = fmaxf(v0, 0.f); v1 = fmaxf(v1, 0.f);
                v2 = fmaxf(v2, 0.f); v3 = fmaxf(v3, 0.f);
            }
            if (SC) { v0 *= s1; v1 *= s1; v2 *= s2; v3 *= s2; }
            if (r1 < M) *(float2*)(C + (size_t)r1 * HH + col) = make_float2(v0, v1);
            if (r2 < M) *(float2*)(C + (size_t)r2 * HH + col) = make_float2(v2, v3);
        }
    }
}

// ---------------- weight split/transpose: W[k][n] fp32 -> Whi/Wlo[n][k] bf16 ----
__global__ void k_wsplit(const float* __restrict__ eW2, const float* __restrict__ cW1,
                         const float* __restrict__ cW2) {
    int m = blockIdx.x >> 8;
    int n = blockIdx.x & 255;
    const float* W = (m == 0) ? eW2
                   : (m <= 3 ? cW1 + (size_t)(m - 1) * 65536 : cW2 + (size_t)(m - 4) * 65536);
    unsigned short* hi = d_wsplit + (size_t)m * 131072 + n * 256;
    unsigned short* lo = hi + 65536;
    for (int k = threadIdx.x; k < 256; k += 64) {
        float w = W[(size_t)k * 256 + n];
        __nv_bfloat16 h = __float2bfloat16_rn(w);
        float r = w - __bfloat162float(h);
        hi[k] = __bfloat16_as_ushort(h);
        lo[k] = __bfloat16_as_ushort(__float2bfloat16_rn(r));
    }
}

// ---------------- small helpers ----------------
__global__ void k_zero_f(float* p, int n) {
    int i = blockIdx.x * blockDim.x + threadIdx.x;
    if (i < n) p[i] = 0.f;
}
__global__ void k_zero_i(int* p, int n) {
    int i = blockIdx.x * blockDim.x + threadIdx.x;
    if (i < n) p[i] = 0;
}

__global__ void k_prep(const float* __restrict__ Wemb, const float* __restrict__ eb,
                       const float* __restrict__ W1, const float* __restrict__ b1,
                       const float* __restrict__ bio, const float* __restrict__ hW1,
                       const float* __restrict__ hb1) {
    int j = threadIdx.x;
    float wc0 = 0.f, wc1 = 0.f, wc2 = 0.f, wc3 = 0.f, bc = 0.f;
    for (int d = 0; d < HH; d++) {
        float w = W1[d * HH + j];
        wc0 += Wemb[0 * HH + d] * w;
        wc1 += Wemb[1 * HH + d] * w;
        wc2 += Wemb[2 * HH + d] * w;
        wc3 += Wemb[3 * HH + d] * w;
        bc  += eb[d] * w;
    }
    d_Wc[0 * HH + j] = wc0;
    d_Wc[1 * HH + j] = wc1;
    d_Wc[2 * HH + j] = wc2;
    d_Wc[3 * HH + j] = wc3;
    d_bc[j] = bc + b1[j];
    float bb = hb1[j];
    for (int k = 0; k < BIOD; k++) bb += bio[k] * hW1[(HH + k) * HH + j];
    d_biob[j] = bb;
}

__global__ void k_node_emb(const int* __restrict__ x, const float* __restrict__ emb) {
    int idx = blockIdx.x * blockDim.x + threadIdx.x;
    int node = idx >> 6;
    int q = idx & 63;
    if (node >= NN) return;
    int xv = x[node];
    float4 v = *(const float4*)(emb + (size_t)xv * HH + q * 4);
    *(float4*)(d_h + (size_t)node * HH + q * 4) = v;
}

// ---------------- CSR build over dst ----------------
__global__ void k_deg(const int* __restrict__ ei) {
    int e = blockIdx.x * blockDim.x + threadIdx.x;
    if (e < EE) atomicAdd(&d_deg[ei[EE + e]], 1);
}
__global__ void k_scan() {
    __shared__ int s[1024];
    int tid = threadIdx.x;
    const int chunk = (NN + 1023) / 1024;
    int beg = tid * chunk;
    int end = min(beg + chunk, NN);
    int sum = 0;
    for (int i = beg; i < end; i++) sum += d_deg[i];
    s[tid] = sum;
    __syncthreads();
    for (int off = 1; off < 1024; off <<= 1) {
        int v = (tid >= off) ? s[tid - off] : 0;
        __syncthreads();
        s[tid] += v;
        __syncthreads();
    }
    int run = (tid > 0) ? s[tid - 1] : 0;
    for (int i = beg; i < end; i++) {
        d_rowptr[i] = run;
        run += d_deg[i];
    }
    if (tid == 1023) d_rowptr[NN] = s[1023];
}
__global__ void k_cursor() {
    int i = blockIdx.x * blockDim.x + threadIdx.x;
    if (i < NN) d_cursor[i] = d_rowptr[i];
}
__global__ void k_fill(const int* __restrict__ ei) {
    int e = blockIdx.x * blockDim.x + threadIdx.x;
    if (e < EE) {
        int dst = ei[EE + e];
        int p = atomicAdd(&d_cursor[dst], 1);
        d_csr[p] = e;
    }
}
__global__ void k_cnt(const int* __restrict__ batch) {
    int i = blockIdx.x * blockDim.x + threadIdx.x;
    if (i < NN) atomicAdd(&d_gcnt[batch[i]], 1.f);
}

// z = (1+eps_l)*h + sum_{e in csr(node)} relu(h[src[e]] + e[e])
__global__ void k_aggregate(const int* __restrict__ ei, const float* __restrict__ conv_eps, int l) {
    int tid = threadIdx.x;
    int node = blockIdx.x * 4 + (tid >> 6);
    int q = tid & 63;
    if (node >= NN) return;
    float eps1 = 1.f + conv_eps[l];
    float4 acc = make_float4(0.f, 0.f, 0.f, 0.f);
    int pbeg = d_rowptr[node];
    int pend = d_rowptr[node + 1];
    for (int p = pbeg; p < pend; p++) {
        int eid = d_csr[p];
        int src = ei[eid];
        float4 hv = *(const float4*)(d_h + (size_t)src * HH + q * 4);
        float4 ev = *(const float4*)(d_e + (size_t)eid * HH + q * 4);
        acc.x += fmaxf(hv.x + ev.x, 0.f);
        acc.y += fmaxf(hv.y + ev.y, 0.f);
        acc.z += fmaxf(hv.z + ev.z, 0.f);
        acc.w += fmaxf(hv.w + ev.w, 0.f);
    }
    float4 hq = *(const float4*)(d_h + (size_t)node * HH + q * 4);
    float4 z;
    z.x = eps1 * hq.x + acc.x;
    z.y = eps1 * hq.y + acc.y;
    z.z = eps1 * hq.z + acc.z;
    z.w = eps1 * hq.w + acc.w;
    *(float4*)(d_z + (size_t)node * HH + q * 4) = z;
}

__global__ void k_seg_sum(const float* __restrict__ src, float* __restrict__ out,
                          const int* __restrict__ batch) {
    int n0 = blockIdx.x * 16;
    int d = threadIdx.x;
    float acc = 0.f;
    int cur = -1;
#pragma unroll 4
    for (int i = 0; i < 16; i++) {
        int node = n0 + i;
        if (node >= NN) break;
        int g = batch[node];
        if (g != cur) {
            if (cur >= 0) atomicAdd(&out[cur * HH + d], acc);
            cur = g;
            acc = 0.f;
        }
        acc += src[(size_t)node * HH + d];
    }
    if (cur >= 0) atomicAdd(&out[cur * HH + d], acc);
}

__global__ void k_seg_var(const int* __restrict__ batch, const float* __restrict__ alpha_l) {
    int n0 = blockIdx.x * 16;
    int d = threadIdx.x;
    float a = alpha_l[d];
    float acc = 0.f, m = 0.f;
    int cur = -1;
#pragma unroll 4
    for (int i = 0; i < 16; i++) {
        int node = n0 + i;
        if (node >= NN) break;
        int g = batch[node];
        if (g != cur) {
            if (cur >= 0) atomicAdd(&d_gvar[cur * HH + d], acc);
            cur = g;
            acc = 0.f;
            m = d_gmean[g * HH + d];
        }
        float hc = d_h[(size_t)node * HH + d] - a * m;
        acc += hc * hc;
    }
    if (cur >= 0) atomicAdd(&d_gvar[cur * HH + d], acc);
}

__global__ void k_fin(float* __restrict__ dst, const float* __restrict__ src, int n) {
    int i = blockIdx.x * blockDim.x + threadIdx.x;
    if (i < n) {
        float c = d_gcnt[i >> 8];
        dst[i] = src[i] / fmaxf(c, 1.f);
    }
}

__global__ void k_norm(const int* __restrict__ batch, const float* __restrict__ gamma,
                       const float* __restrict__ beta, const float* __restrict__ alpha, int l) {
    int idx = blockIdx.x * blockDim.x + threadIdx.x;
    int node = idx >> 6;
    int q = idx & 63;
    if (node >= NN) return;
    int g = batch[node];
    float4 h = *(const float4*)(d_h + (size_t)node * HH + q * 4);
    float4 m = *(const float4*)(d_gmean + g * HH + q * 4);
    float4 v = *(const float4*)(d_gvar + g * HH + q * 4);
    float4 ga = *(const float4*)(gamma + l * HH + q * 4);
    float4 be = *(const float4*)(beta + l * HH + q * 4);
    float4 al = *(const float4*)(alpha + l * HH + q * 4);
    h.x = ga.x * (h.x - al.x * m.x) * rsqrtf(v.x + GEPS) + be.x;
    h.y = ga.y * (h.y - al.y * m.y) * rsqrtf(v.y + GEPS) + be.y;
    h.z = ga.z * (h.z - al.z * m.z) * rsqrtf(v.z + GEPS) + be.z;
    h.w = ga.w * (h.w - al.w * m.w) * rsqrtf(v.w + GEPS) + be.w;
    *(float4*)(d_h + (size_t)node * HH + q * 4) = h;
}

__global__ void k_head(const float* __restrict__ hW1, const float* __restrict__ hW2,
                       const float* __restrict__ hb2, float* __restrict__ out) {
    int g = blockIdx.x;
    int j = threadIdx.x;
    __shared__ float red[256];
    float acc = d_biob[j];
    const float* grow = d_gpool + g * HH;
    for (int k = 0; k < HH; k++) acc += grow[k] * hW1[k * HH + j];
    red[j] = fmaxf(acc, 0.f) * hW2[j];
    __syncthreads();
    for (int off = 128; off > 0; off >>= 1) {
        if (j < off) red[j] += red[j + off];
        __syncthreads();
    }
    if (j == 0) out[g] = red[0] + hb2[0];
}

// ---------------- launch ----------------
extern "C" void kernel_launch(void* const* d_in, const int* in_sizes, int n_in,
                              void* d_out, int out_size) {
    const int* x = (const int*)d_in[0];
    const int* ei = (const int*)d_in[1];
    const float* edge_attr = (const float*)d_in[2];
    const int* batch = (const int*)d_in[3];
    const float* node_emb_W = (const float*)d_in[4];
    const float* edge_emb_W = (const float*)d_in[5];
    const float* edge_emb_b = (const float*)d_in[6];
    const float* edge_mlp_W1 = (const float*)d_in[7];
    const float* edge_mlp_b1 = (const float*)d_in[8];
    const float* edge_mlp_W2 = (const float*)d_in[9];
    const float* edge_mlp_b2 = (const float*)d_in[10];
    const float* struct_scale = (const float*)d_in[11];
    const float* conv_W1 = (const float*)d_in[12];
    const float* conv_b1 = (const float*)d_in[13];
    const float* conv_W2 = (const float*)d_in[14];
    const float* conv_b2 = (const float*)d_in[15];
    const float* conv_eps = (const float*)d_in[16];
    const float* norm_gamma = (const float*)d_in[17];
    const float* norm_beta = (const float*)d_in[18];
    const float* norm_alpha = (const float*)d_in[19];
    const float* mean_bio = (const float*)d_in[20];
    const float* head_W1 = (const float*)d_in[21];
    const float* head_b1 = (const float*)d_in[22];
    const float* head_W2 = (const float*)d_in[23];
    const float* head_b2 = (const float*)d_in[24];
    float* out = (float*)d_out;
    (void)in_sizes; (void)n_in; (void)out_size;

    float *g_gsum, *g_gvar, *g_gmean, *g_gcnt, *g_gpool, *g_e, *g_z, *g_t, *g_h;
    int* g_deg;
    unsigned short* g_wsp;
    cudaGetSymbolAddress((void**)&g_gsum, d_gsum);
    cudaGetSymbolAddress((void**)&g_gvar, d_gvar);
    cudaGetSymbolAddress((void**)&g_gmean, d_gmean);
    cudaGetSymbolAddress((void**)&g_gcnt, d_gcnt);
    cudaGetSymbolAddress((void**)&g_gpool, d_gpool);
    cudaGetSymbolAddress((void**)&g_e, d_e);
    cudaGetSymbolAddress((void**)&g_z, d_z);
    cudaGetSymbolAddress((void**)&g_t, d_t);
    cudaGetSymbolAddress((void**)&g_h, d_h);
    cudaGetSymbolAddress((void**)&g_deg, d_deg);
    cudaGetSymbolAddress((void**)&g_wsp, d_wsplit);

    cudaFuncSetAttribute(k_mma<true, false, true>,
                         cudaFuncAttributeMaxDynamicSharedMemorySize, SMEM_BYTES);
    cudaFuncSetAttribute(k_mma<false, true, false>,
                         cudaFuncAttributeMaxDynamicSharedMemorySize, SMEM_BYTES);
    cudaFuncSetAttribute(k_mma<false, false, false>,
                         cudaFuncAttributeMaxDynamicSharedMemorySize, SMEM_BYTES);

    // 1. fold small weights; split/transpose big weights to bf16 hi/lo
    k_prep<<<1, 256>>>(edge_emb_W, edge_emb_b, edge_mlp_W1, edge_mlp_b1,
                       mean_bio, head_W1, head_b1);
    k_wsplit<<<7 * 256, 64>>>(edge_mlp_W2, conv_W1, conv_W2);
    // 2. node embedding
    k_node_emb<<<(NN * 64 + 255) / 256, 256>>>(x, node_emb_W);
    // 3. edge features: e = (relu(attr@Wc+bc) @ W2 + b2) * struct  — fused tensor GEMM
    k_mma<true, false, true><<<dim3(EE / 128, 2), 256, SMEM_BYTES>>>(
        nullptr, edge_attr, g_wsp, edge_mlp_b2, struct_scale, g_e, EE);
    // 4. CSR build
    k_zero_i<<<(NN + 255) / 256, 256>>>(g_deg, NN);
    k_deg<<<(EE + 255) / 256, 256>>>(ei);
    k_scan<<<1, 1024>>>();
    k_cursor<<<(NN + 255) / 256, 256>>>();
    k_fill<<<(EE + 255) / 256, 256>>>(ei);
    // 5. per-graph counts
    k_zero_f<<<1, 256>>>(g_gcnt, GG);
    k_cnt<<<(NN + 255) / 256, 256>>>(batch);

    const int mb = (NN + 127) / 128;
    for (int l = 0; l < 3; l++) {
        k_aggregate<<<(NN + 3) / 4, 256>>>(ei, conv_eps, l);
        k_mma<false, true, false><<<dim3(mb, 2), 256, SMEM_BYTES>>>(
            g_z, nullptr, g_wsp + (size_t)(1 + l) * 131072, conv_b1 + l * HH, nullptr, g_t, NN);
        k_mma<false, false, false><<<dim3(mb, 2), 256, SMEM_BYTES>>>(
            g_t, nullptr, g_wsp + (size_t)(4 + l) * 131072, conv_b2 + l * HH, nullptr, g_h, NN);
        // GraphNorm
        k_zero_f<<<(GG * HH + 255) / 256, 256>>>(g_gsum, GG * HH);
        k_seg_sum<<<(NN + 15) / 16, 256>>>(g_h, g_gsum, batch);
        k_fin<<<(GG * HH + 255) / 256, 256>>>(g_gmean, g_gsum, GG * HH);
        k_zero_f<<<(GG * HH + 255) / 256, 256>>>(g_gvar, GG * HH);
        k_seg_var<<<(NN + 15) / 16, 256>>>(batch, norm_alpha + l * HH);
        k_fin<<<(GG * HH + 255) / 256, 256>>>(g_gvar, g_gvar, GG * HH);
        k_norm<<<(NN * 64 + 255) / 256, 256>>>(batch, norm_gamma, norm_beta, norm_alpha, l);
    }

    // 6. mean pool + head
    k_zero_f<<<(GG * HH + 255) / 256, 256>>>(g_gsum, GG * HH);
    k_seg_sum<<<(NN + 15) / 16, 256>>>(g_h, g_gsum, batch);
    k_fin<<<(GG * HH + 255) / 256, 256>>>(g_gpool, g_gsum, GG * HH);
    k_head<<<GG, 256>>>(head_W1, head_W2, head_b2, out);
}

// round 4
// speedup vs baseline: 1.6166x; 1.1463x over previous
#include <cuda_runtime.h>
#include <cuda_bf16.h>
#include <cstdint>

#define NN 100000
#define EE 400000
#define GG 256
#define HH 256
#define BIOD 512
#define GEPS 1e-5f

// ---------------- scratch (device globals; no allocation in kernel_launch) -----
static __device__ float d_h[(size_t)NN * HH];
static __device__ float d_z[(size_t)NN * HH];
static __device__ float d_t[(size_t)NN * HH];
static __device__ float d_e[(size_t)EE * HH];
static __device__ int   d_deg[NN];
static __device__ int   d_rowptr[NN + 1];
static __device__ int   d_cursor[NN];
static __device__ int   d_csr[EE];
static __device__ float d_Wc[4 * HH];
static __device__ float d_bc[HH];
static __device__ float d_biob[HH];
static __device__ float d_gsum[GG * HH];
static __device__ float d_gvar[GG * HH];
static __device__ float d_gmean[GG * HH];
static __device__ float d_gcnt[GG];
static __device__ float d_gpool[GG * HH];
// 7 weight matrices x (hi, lo) x 256x256 bf16, layout [mat][hi/lo][n][k]
static __device__ unsigned short d_wsplit[(size_t)7 * 2 * 65536];

// ---------------- mma helpers ----------------
__device__ __forceinline__ uint32_t smem_to_u32(const void* smem_ptr) {
    uint32_t addr;
    asm("{ .reg .u64 tmp; cvta.to.shared.u64 tmp, %1; cvt.u32.u64 %0, tmp; }"
        : "=r"(addr) : "l"(smem_ptr));
    return addr;
}
__device__ __forceinline__ void ldsm4(unsigned* r, uint32_t addr) {
    asm volatile("ldmatrix.sync.aligned.m8n8.x4.shared.b16 {%0,%1,%2,%3}, [%4];"
                 : "=r"(r[0]), "=r"(r[1]), "=r"(r[2]), "=r"(r[3]) : "r"(addr));
}
__device__ __forceinline__ void ldsm2(unsigned* r, uint32_t addr) {
    asm volatile("ldmatrix.sync.aligned.m8n8.x2.shared.b16 {%0,%1}, [%2];"
                 : "=r"(r[0]), "=r"(r[1]) : "r"(addr));
}
__device__ __forceinline__ void mma16816(float* d, const unsigned* a, const unsigned* b) {
    asm volatile(
        "mma.sync.aligned.m16n8k16.row.col.f32.bf16.bf16.f32 "
        "{%0,%1,%2,%3}, {%4,%5,%6,%7}, {%8,%9}, {%0,%1,%2,%3};"
        : "+f"(d[0]), "+f"(d[1]), "+f"(d[2]), "+f"(d[3])
        : "r"(a[0]), "r"(a[1]), "r"(a[2]), "r"(a[3]), "r"(b[0]), "r"(b[1]));
}
// round 2 floats to a packed bf16x2 word
__device__ __forceinline__ unsigned pack2(float a, float b) {
    return (unsigned)__bfloat16_as_ushort(__float2bfloat16_rn(a)) |
           ((unsigned)__bfloat16_as_ushort(__float2bfloat16_rn(b)) << 16);
}

// ============================================================================
// bf16 tensor-core GEMM (A single-bf16, W split hi+lo -> 2 MMA terms):
//   C[M,256] = op(A[M,256] @ W[256,256] + bias)
// AF: A computed on the fly as relu(attr@Wc+bc) (edge MLP layer-1 fused)
// RELU: relu epilogue; SC: per-row struct-scale from attr[:,1].
// Block 128x128, BK=64, 8 warps (2m x 4n), warp tile 64x32 (mt=4, nt=4).
// SMEM: A hi [128x72], B hi [128x72], B lo [128x72] bf16 (pitch 72 = bank-clean)
// ============================================================================
#define PITCH 72
#define SMEM_BYTES (3 * 128 * PITCH * 2)   // 55296

template <bool AF, bool RELU, bool SC>
__global__ __launch_bounds__(256, 2) void k_mma(
    const float* __restrict__ A, const float* __restrict__ attr,
    const unsigned short* __restrict__ Wsp,  // [hi 65536][lo 65536], [n][k]
    const float* __restrict__ bias, const float* __restrict__ sscale,
    float* __restrict__ C, int M) {
    extern __shared__ __nv_bfloat16 smbf[];
    __nv_bfloat16* sA   = smbf;            // 9216 elems
    __nv_bfloat16* sBhi = smbf + 9216;
    __nv_bfloat16* sBlo = smbf + 18432;
    const uint32_t sbase = smem_to_u32(smbf);

    int tid = threadIdx.x;
    int lane = tid & 31, wid = tid >> 5;
    int wm = wid >> 2, wn = wid & 3;       // 2m x 4n; warp tile 64x32
    int row0 = blockIdx.x * 128;
    int n0 = blockIdx.y * 128;
    const unsigned short* Whi = Wsp;
    const unsigned short* Wlo = Wsp + 65536;

    float acc[4][4][4];
#pragma unroll
    for (int mt = 0; mt < 4; mt++)
#pragma unroll
        for (int nt = 0; nt < 4; nt++)
#pragma unroll
            for (int j = 0; j < 4; j++) acc[mt][nt][j] = 0.f;

    for (int c = 0; c < 4; c++) {
        int k0 = c * 64;
        // ---- stage B chunk [128 n][64 k] hi+lo ----
        {
            int n = tid >> 1, kh = (tid & 1) * 32;
            const unsigned short* ph = Whi + (size_t)(n0 + n) * 256 + k0 + kh;
            const unsigned short* pl = Wlo + (size_t)(n0 + n) * 256 + k0 + kh;
#pragma unroll
            for (int j = 0; j < 4; j++) {
                uint4 vh = *(const uint4*)(ph + j * 8);
                uint4 vl = *(const uint4*)(pl + j * 8);
                *(uint4*)&sBhi[n * PITCH + kh + j * 8] = vh;
                *(uint4*)&sBlo[n * PITCH + kh + j * 8] = vl;
            }
        }
        // ---- stage A chunk [128 m][64 k] single bf16 ----
        {
            int r = tid >> 1, kh = (tid & 1) * 32;
            if (AF) {
                float4 a = *(const float4*)(attr + (size_t)(row0 + r) * 4);
#pragma unroll
                for (int j = 0; j < 16; j++) {
                    int k = k0 + kh + 2 * j;
                    float v0 = fmaxf(a.x * d_Wc[k] + a.y * d_Wc[256 + k] +
                                     a.z * d_Wc[512 + k] + a.w * d_Wc[768 + k] + d_bc[k], 0.f);
                    float v1 = fmaxf(a.x * d_Wc[k + 1] + a.y * d_Wc[257 + k] +
                                     a.z * d_Wc[513 + k] + a.w * d_Wc[769 + k] + d_bc[k + 1], 0.f);
                    *(unsigned*)&sA[r * PITCH + kh + 2 * j] = pack2(v0, v1);
                }
            } else {
                bool ok = (row0 + r) < M;
                const float* Ar = A + (size_t)(row0 + r) * HH + k0 + kh;
#pragma unroll
                for (int q = 0; q < 8; q++) {
                    float4 v = ok ? *(const float4*)(Ar + q * 4) : make_float4(0.f, 0.f, 0.f, 0.f);
                    uint2 w;
                    w.x = pack2(v.x, v.y);
                    w.y = pack2(v.z, v.w);
                    *(uint2*)&sA[r * PITCH + kh + q * 4] = w;
                }
            }
        }
        __syncthreads();

        // ---- compute: 4 k16-steps; 2 split-products each ----
#pragma unroll
        for (int ks = 0; ks < 64; ks += 16) {
            unsigned fA[4][4];
#pragma unroll
            for (int mt = 0; mt < 4; mt++) {
                int mrow = wm * 64 + mt * 16 + (lane & 15);
                uint32_t off = (uint32_t)(mrow * PITCH + ks + ((lane >> 4) << 3)) * 2;
                ldsm4(fA[mt], sbase + off);
            }
#pragma unroll
            for (int nt = 0; nt < 4; nt++) {
                int l = lane & 15;
                int nrow = wn * 32 + nt * 8 + (l & 7);
                uint32_t off = (uint32_t)(nrow * PITCH + ks + ((l & 8) ? 8 : 0)) * 2;
                unsigned fBh[2], fBl[2];
                ldsm2(fBh, sbase + 18432 + off);
                ldsm2(fBl, sbase + 36864 + off);
#pragma unroll
                for (int mt = 0; mt < 4; mt++) {
                    mma16816(acc[mt][nt], fA[mt], fBh);
                    mma16816(acc[mt][nt], fA[mt], fBl);
                }
            }
        }
        __syncthreads();
    }

    // ---- epilogue: bias / relu / struct-scale, direct stores ----
#pragma unroll
    for (int mt = 0; mt < 4; mt++) {
        int r1 = row0 + wm * 64 + mt * 16 + (lane >> 2);
        int r2 = r1 + 8;
        float s1 = 1.f, s2 = 1.f;
        if (SC) {
            float ssv = __ldg(sscale);
            s1 = (attr[(size_t)r1 * 4 + 1] > 0.f) ? ssv : 1.f;
            s2 = (attr[(size_t)r2 * 4 + 1] > 0.f) ? ssv : 1.f;
        }
#pragma unroll
        for (int nt = 0; nt < 4; nt++) {
            int col = n0 + wn * 32 + nt * 8 + 2 * (lane & 3);
            float2 b = *(const float2*)(bias + col);
            float v0 = acc[mt][nt][0] + b.x, v1 = acc[mt][nt][1] + b.y;
            float v2 = acc[mt][nt][2] + b.x, v3 = acc[mt][nt][3] + b.y;
            if (RELU) {
                v0 = fmaxf(v0, 0.f); v1 = fmaxf(v1, 0.f);
                v2 = fmaxf(v2, 0.f); v3 = fmaxf(v3, 0.f);
            }
            if (SC) { v0 *= s1; v1 *= s1; v2 *= s2; v3 *= s2; }
            if (r1 < M) *(float2*)(C + (size_t)r1 * HH + col) = make_float2(v0, v1);
            if (r2 < M) *(float2*)(C + (size_t)r2 * HH + col) = make_float2(v2, v3);
        }
    }
}

// ---------------- weight split/transpose: W[k][n] fp32 -> Whi/Wlo[n][k] bf16 ----
__global__ void k_wsplit(const float* __restrict__ eW2, const float* __restrict__ cW1,
                         const float* __restrict__ cW2) {
    int m = blockIdx.x >> 8;
    int n = blockIdx.x & 255;
    const float* W = (m == 0) ? eW2
                   : (m <= 3 ? cW1 + (size_t)(m - 1) * 65536 : cW2 + (size_t)(m - 4) * 65536);
    unsigned short* hi = d_wsplit + (size_t)m * 131072 + n * 256;
    unsigned short* lo = hi + 65536;
    for (int k = threadIdx.x; k < 256; k += 64) {
        float w = W[(size_t)k * 256 + n];
        __nv_bfloat16 h = __float2bfloat16_rn(w);
        float r = w - __bfloat162float(h);
        hi[k] = __bfloat16_as_ushort(h);
        lo[k] = __bfloat16_as_ushort(__float2bfloat16_rn(r));
    }
}

// ---------------- small helpers ----------------
__global__ void k_zero_f(float* p, int n) {
    int i = blockIdx.x * blockDim.x + threadIdx.x;
    if (i < n) p[i] = 0.f;
}
__global__ void k_zero_i(int* p, int n) {
    int i = blockIdx.x * blockDim.x + threadIdx.x;
    if (i < n) p[i] = 0;
}

__global__ void k_prep(const float* __restrict__ Wemb, const float* __restrict__ eb,
                       const float* __restrict__ W1, const float* __restrict__ b1,
                       const float* __restrict__ bio, const float* __restrict__ hW1,
                       const float* __restrict__ hb1) {
    int j = threadIdx.x;
    float wc0 = 0.f, wc1 = 0.f, wc2 = 0.f, wc3 = 0.f, bc = 0.f;
    for (int d = 0; d < HH; d++) {
        float w = W1[d * HH + j];
        wc0 += Wemb[0 * HH + d] * w;
        wc1 += Wemb[1 * HH + d] * w;
        wc2 += Wemb[2 * HH + d] * w;
        wc3 += Wemb[3 * HH + d] * w;
        bc  += eb[d] * w;
    }
    d_Wc[0 * HH + j] = wc0;
    d_Wc[1 * HH + j] = wc1;
    d_Wc[2 * HH + j] = wc2;
    d_Wc[3 * HH + j] = wc3;
    d_bc[j] = bc + b1[j];
    float bb = hb1[j];
    for (int k = 0; k < BIOD; k++) bb += bio[k] * hW1[(HH + k) * HH + j];
    d_biob[j] = bb;
}

__global__ void k_node_emb(const int* __restrict__ x, const float* __restrict__ emb) {
    int idx = blockIdx.x * blockDim.x + threadIdx.x;
    int node = idx >> 6;
    int q = idx & 63;
    if (node >= NN) return;
    int xv = x[node];
    float4 v = *(const float4*)(emb + (size_t)xv * HH + q * 4);
    *(float4*)(d_h + (size_t)node * HH + q * 4) = v;
}

// ---------------- CSR build over dst ----------------
__global__ void k_deg(const int* __restrict__ ei) {
    int e = blockIdx.x * blockDim.x + threadIdx.x;
    if (e < EE) atomicAdd(&d_deg[ei[EE + e]], 1);
}
__global__ void k_scan() {
    __shared__ int s[1024];
    int tid = threadIdx.x;
    const int chunk = (NN + 1023) / 1024;
    int beg = tid * chunk;
    int end = min(beg + chunk, NN);
    int sum = 0;
    for (int i = beg; i < end; i++) sum += d_deg[i];
    s[tid] = sum;
    __syncthreads();
    for (int off = 1; off < 1024; off <<= 1) {
        int v = (tid >= off) ? s[tid - off] : 0;
        __syncthreads();
        s[tid] += v;
        __syncthreads();
    }
    int run = (tid > 0) ? s[tid - 1] : 0;
    for (int i = beg; i < end; i++) {
        d_rowptr[i] = run;
        run += d_deg[i];
    }
    if (tid == 1023) d_rowptr[NN] = s[1023];
}
__global__ void k_cursor() {
    int i = blockIdx.x * blockDim.x + threadIdx.x;
    if (i < NN) d_cursor[i] = d_rowptr[i];
}
__global__ void k_fill(const int* __restrict__ ei) {
    int e = blockIdx.x * blockDim.x + threadIdx.x;
    if (e < EE) {
        int dst = ei[EE + e];
        int p = atomicAdd(&d_cursor[dst], 1);
        d_csr[p] = e;
    }
}
__global__ void k_cnt(const int* __restrict__ batch) {
    int i = blockIdx.x * blockDim.x + threadIdx.x;
    if (i < NN) atomicAdd(&d_gcnt[batch[i]], 1.f);
}

// z = (1+eps_l)*h + sum_{e in csr(node)} relu(h[src[e]] + e[e])
__global__ void k_aggregate(const int* __restrict__ ei, const float* __restrict__ conv_eps, int l) {
    int tid = threadIdx.x;
    int node = blockIdx.x * 4 + (tid >> 6);
    int q = tid & 63;
    if (node >= NN) return;
    float eps1 = 1.f + conv_eps[l];
    float4 acc = make_float4(0.f, 0.f, 0.f, 0.f);
    int pbeg = d_rowptr[node];
    int pend = d_rowptr[node + 1];
    for (int p = pbeg; p < pend; p++) {
        int eid = d_csr[p];
        int src = ei[eid];
        float4 hv = *(const float4*)(d_h + (size_t)src * HH + q * 4);
        float4 ev = *(const float4*)(d_e + (size_t)eid * HH + q * 4);
        acc.x += fmaxf(hv.x + ev.x, 0.f);
        acc.y += fmaxf(hv.y + ev.y, 0.f);
        acc.z += fmaxf(hv.z + ev.z, 0.f);
        acc.w += fmaxf(hv.w + ev.w, 0.f);
    }
    float4 hq = *(const float4*)(d_h + (size_t)node * HH + q * 4);
    float4 z;
    z.x = eps1 * hq.x + acc.x;
    z.y = eps1 * hq.y + acc.y;
    z.z = eps1 * hq.z + acc.z;
    z.w = eps1 * hq.w + acc.w;
    *(float4*)(d_z + (size_t)node * HH + q * 4) = z;
}

__global__ void k_seg_sum(const float* __restrict__ src, float* __restrict__ out,
                          const int* __restrict__ batch) {
    int n0 = blockIdx.x * 16;
    int d = threadIdx.x;
    float acc = 0.f;
    int cur = -1;
#pragma unroll 4
    for (int i = 0; i < 16; i++) {
        int node = n0 + i;
        if (node >= NN) break;
        int g = batch[node];
        if (g != cur) {
            if (cur >= 0) atomicAdd(&out[cur * HH + d], acc);
            cur = g;
            acc = 0.f;
        }
        acc += src[(size_t)node * HH + d];
    }
    if (cur >= 0) atomicAdd(&out[cur * HH + d], acc);
}

__global__ void k_seg_var(const int* __restrict__ batch, const float* __restrict__ alpha_l) {
    int n0 = blockIdx.x * 16;
    int d = threadIdx.x;
    float a = alpha_l[d];
    float acc = 0.f, m = 0.f;
    int cur = -1;
#pragma unroll 4
    for (int i = 0; i < 16; i++) {
        int node = n0 + i;
        if (node >= NN) break;
        int g = batch[node];
        if (g != cur) {
            if (cur >= 0) atomicAdd(&d_gvar[cur * HH + d], acc);
            cur = g;
            acc = 0.f;
            m = d_gmean[g * HH + d];
        }
        float hc = d_h[(size_t)node * HH + d] - a * m;
        acc += hc * hc;
    }
    if (cur >= 0) atomicAdd(&d_gvar[cur * HH + d], acc);
}

__global__ void k_fin(float* __restrict__ dst, const float* __restrict__ src, int n) {
    int i = blockIdx.x * blockDim.x + threadIdx.x;
    if (i < n) {
        float c = d_gcnt[i >> 8];
        dst[i] = src[i] / fmaxf(c, 1.f);
    }
}

__global__ void k_norm(const int* __restrict__ batch, const float* __restrict__ gamma,
                       const float* __restrict__ beta, const float* __restrict__ alpha, int l) {
    int idx = blockIdx.x * blockDim.x + threadIdx.x;
    int node = idx >> 6;
    int q = idx & 63;
    if (node >= NN) return;
    int g = batch[node];
    float4 h = *(const float4*)(d_h + (size_t)node * HH + q * 4);
    float4 m = *(const float4*)(d_gmean + g * HH + q * 4);
    float4 v = *(const float4*)(d_gvar + g * HH + q * 4);
    float4 ga = *(const float4*)(gamma + l * HH + q * 4);
    float4 be = *(const float4*)(beta + l * HH + q * 4);
    float4 al = *(const float4*)(alpha + l * HH + q * 4);
    h.x = ga.x * (h.x - al.x * m.x) * rsqrtf(v.x + GEPS) + be.x;
    h.y = ga.y * (h.y - al.y * m.y) * rsqrtf(v.y + GEPS) + be.y;
    h.z = ga.z * (h.z - al.z * m.z) * rsqrtf(v.z + GEPS) + be.z;
    h.w = ga.w * (h.w - al.w * m.w) * rsqrtf(v.w + GEPS) + be.w;
    *(float4*)(d_h + (size_t)node * HH + q * 4) = h;
}

__global__ void k_head(const float* __restrict__ hW1, const float* __restrict__ hW2,
                       const float* __restrict__ hb2, float* __restrict__ out) {
    int g = blockIdx.x;
    int j = threadIdx.x;
    __shared__ float red[256];
    float acc = d_biob[j];
    const float* grow = d_gpool + g * HH;
    for (int k = 0; k < HH; k++) acc += grow[k] * hW1[k * HH + j];
    red[j] = fmaxf(acc, 0.f) * hW2[j];
    __syncthreads();
    for (int off = 128; off > 0; off >>= 1) {
        if (j < off) red[j] += red[j + off];
        __syncthreads();
    }
    if (j == 0) out[g] = red[0] + hb2[0];
}

// ---------------- launch ----------------
extern "C" void kernel_launch(void* const* d_in, const int* in_sizes, int n_in,
                              void* d_out, int out_size) {
    const int* x = (const int*)d_in[0];
    const int* ei = (const int*)d_in[1];
    const float* edge_attr = (const float*)d_in[2];
    const int* batch = (const int*)d_in[3];
    const float* node_emb_W = (const float*)d_in[4];
    const float* edge_emb_W = (const float*)d_in[5];
    const float* edge_emb_b = (const float*)d_in[6];
    const float* edge_mlp_W1 = (const float*)d_in[7];
    const float* edge_mlp_b1 = (const float*)d_in[8];
    const float* edge_mlp_W2 = (const float*)d_in[9];
    const float* edge_mlp_b2 = (const float*)d_in[10];
    const float* struct_scale = (const float*)d_in[11];
    const float* conv_W1 = (const float*)d_in[12];
    const float* conv_b1 = (const float*)d_in[13];
    const float* conv_W2 = (const float*)d_in[14];
    const float* conv_b2 = (const float*)d_in[15];
    const float* conv_eps = (const float*)d_in[16];
    const float* norm_gamma = (const float*)d_in[17];
    const float* norm_beta = (const float*)d_in[18];
    const float* norm_alpha = (const float*)d_in[19];
    const float* mean_bio = (const float*)d_in[20];
    const float* head_W1 = (const float*)d_in[21];
    const float* head_b1 = (const float*)d_in[22];
    const float* head_W2 = (const float*)d_in[23];
    const float* head_b2 = (const float*)d_in[24];
    float* out = (float*)d_out;
    (void)in_sizes; (void)n_in; (void)out_size;

    float *g_gsum, *g_gvar, *g_gmean, *g_gcnt, *g_gpool, *g_e, *g_z, *g_t, *g_h;
    int* g_deg;
    unsigned short* g_wsp;
    cudaGetSymbolAddress((void**)&g_gsum, d_gsum);
    cudaGetSymbolAddress((void**)&g_gvar, d_gvar);
    cudaGetSymbolAddress((void**)&g_gmean, d_gmean);
    cudaGetSymbolAddress((void**)&g_gcnt, d_gcnt);
    cudaGetSymbolAddress((void**)&g_gpool, d_gpool);
    cudaGetSymbolAddress((void**)&g_e, d_e);
    cudaGetSymbolAddress((void**)&g_z, d_z);
    cudaGetSymbolAddress((void**)&g_t, d_t);
    cudaGetSymbolAddress((void**)&g_h, d_h);
    cudaGetSymbolAddress((void**)&g_deg, d_deg);
    cudaGetSymbolAddress((void**)&g_wsp, d_wsplit);

    cudaFuncSetAttribute(k_mma<true, false, true>,
                         cudaFuncAttributeMaxDynamicSharedMemorySize, SMEM_BYTES);
    cudaFuncSetAttribute(k_mma<false, true, false>,
                         cudaFuncAttributeMaxDynamicSharedMemorySize, SMEM_BYTES);
    cudaFuncSetAttribute(k_mma<false, false, false>,
                         cudaFuncAttributeMaxDynamicSharedMemorySize, SMEM_BYTES);

    // 1. fold small weights; split/transpose big weights to bf16 hi/lo
    k_prep<<<1, 256>>>(edge_emb_W, edge_emb_b, edge_mlp_W1, edge_mlp_b1,
                       mean_bio, head_W1, head_b1);
    k_wsplit<<<7 * 256, 64>>>(edge_mlp_W2, conv_W1, conv_W2);
    // 2. node embedding
    k_node_emb<<<(NN * 64 + 255) / 256, 256>>>(x, node_emb_W);
    // 3. edge features: e = (relu(attr@Wc+bc) @ W2 + b2) * struct  — fused tensor GEMM
    k_mma<true, false, true><<<dim3(EE / 128, 2), 256, SMEM_BYTES>>>(
        nullptr, edge_attr, g_wsp, edge_mlp_b2, struct_scale, g_e, EE);
    // 4. CSR build
    k_zero_i<<<(NN + 255) / 256, 256>>>(g_deg, NN);
    k_deg<<<(EE + 255) / 256, 256>>>(ei);
    k_scan<<<1, 1024>>>();
    k_cursor<<<(NN + 255) / 256, 256>>>();
    k_fill<<<(EE + 255) / 256, 256>>>(ei);
    // 5. per-graph counts
    k_zero_f<<<1, 256>>>(g_gcnt, GG);
    k_cnt<<<(NN + 255) / 256, 256>>>(batch);

    const int mb = (NN + 127) / 128;
    for (int l = 0; l < 3; l++) {
        k_aggregate<<<(NN + 3) / 4, 256>>>(ei, conv_eps, l);
        k_mma<false, true, false><<<dim3(mb, 2), 256, SMEM_BYTES>>>(
            g_z, nullptr, g_wsp + (size_t)(1 + l) * 131072, conv_b1 + l * HH, nullptr, g_t, NN);
        k_mma<false, false, false><<<dim3(mb, 2), 256, SMEM_BYTES>>>(
            g_t, nullptr, g_wsp + (size_t)(4 + l) * 131072, conv_b2 + l * HH, nullptr, g_h, NN);
        // GraphNorm
        k_zero_f<<<(GG * HH + 255) / 256, 256>>>(g_gsum, GG * HH);
        k_seg_sum<<<(NN + 15) / 16, 256>>>(g_h, g_gsum, batch);
        k_fin<<<(GG * HH + 255) / 256, 256>>>(g_gmean, g_gsum, GG * HH);
        k_zero_f<<<(GG * HH + 255) / 256, 256>>>(g_gvar, GG * HH);
        k_seg_var<<<(NN + 15) / 16, 256>>>(batch, norm_alpha + l * HH);
        k_fin<<<(GG * HH + 255) / 256, 256>>>(g_gvar, g_gvar, GG * HH);
        k_norm<<<(NN * 64 + 255) / 256, 256>>>(batch, norm_gamma, norm_beta, norm_alpha, l);
    }

    // 6. mean pool + head
    k_zero_f<<<(GG * HH + 255) / 256, 256>>>(g_gsum, GG * HH);
    k_seg_sum<<<(NN + 15) / 16, 256>>>(g_h, g_gsum, batch);
    k_fin<<<(GG * HH + 255) / 256, 256>>>(g_gpool, g_gsum, GG * HH);
    k_head<<<GG, 256>>>(head_W1, head_W2, head_b2, out);
}

// round 5
// speedup vs baseline: 2.1787x; 1.3477x over previous
#include <cuda_runtime.h>
#include <cuda_fp16.h>
#include <cstdint>

#define NN 100000
#define EE 400000
#define GG 256
#define HH 256
#define BIOD 512
#define GEPS 1e-5f

// ---------------- scratch (device globals) ----------------
static __device__ __half d_h[(size_t)NN * HH];
static __device__ __half d_z[(size_t)NN * HH];
static __device__ __half d_t[(size_t)NN * HH];
static __device__ __half d_e[(size_t)EE * HH];
static __device__ int    d_deg[NN];
static __device__ int    d_rowptr[NN + 1];
static __device__ int    d_cursor[NN];
static __device__ int    d_csr[EE];
static __device__ float  d_Wc[4 * HH];
static __device__ float  d_bc[HH];
static __device__ float  d_biob[HH];
static __device__ float  d_gsum[GG * HH];
static __device__ float  d_gsumsq[GG * HH];
static __device__ float  d_gvar[GG * HH];
static __device__ float  d_gmean[GG * HH];
static __device__ float  d_gcnt[GG];
static __device__ float  d_gpool[GG * HH];
// 7 weight matrices x (hi, lo) x 256x256 fp16, layout [mat][hi/lo][n][k]
static __device__ unsigned short d_wsplit[(size_t)7 * 2 * 65536];

// ---------------- asm helpers ----------------
__device__ __forceinline__ uint32_t smem_to_u32(const void* smem_ptr) {
    uint32_t addr;
    asm("{ .reg .u64 tmp; cvta.to.shared.u64 tmp, %1; cvt.u32.u64 %0, tmp; }"
        : "=r"(addr) : "l"(smem_ptr));
    return addr;
}
__device__ __forceinline__ void ldsm4(unsigned* r, uint32_t addr) {
    asm volatile("ldmatrix.sync.aligned.m8n8.x4.shared.b16 {%0,%1,%2,%3}, [%4];"
                 : "=r"(r[0]), "=r"(r[1]), "=r"(r[2]), "=r"(r[3]) : "r"(addr));
}
__device__ __forceinline__ void ldsm2(unsigned* r, uint32_t addr) {
    asm volatile("ldmatrix.sync.aligned.m8n8.x2.shared.b16 {%0,%1}, [%2];"
                 : "=r"(r[0]), "=r"(r[1]) : "r"(addr));
}
__device__ __forceinline__ void mma16816(float* d, const unsigned* a, const unsigned* b) {
    asm volatile(
        "mma.sync.aligned.m16n8k16.row.col.f32.f16.f16.f32 "
        "{%0,%1,%2,%3}, {%4,%5,%6,%7}, {%8,%9}, {%0,%1,%2,%3};"
        : "+f"(d[0]), "+f"(d[1]), "+f"(d[2]), "+f"(d[3])
        : "r"(a[0]), "r"(a[1]), "r"(a[2]), "r"(a[3]), "r"(b[0]), "r"(b[1]));
}
__device__ __forceinline__ void cpasync16(uint32_t dst, const void* src) {
    asm volatile("cp.async.ca.shared.global [%0], [%1], 16;" :: "r"(dst), "l"(src));
}
#define CP_COMMIT() asm volatile("cp.async.commit_group;" ::: "memory")
#define CP_WAIT0()  asm volatile("cp.async.wait_group 0;" ::: "memory")

// pack 2 floats -> fp16x2 word
__device__ __forceinline__ unsigned pack2(float a, float b) {
    __half2 h = __floats2half2_rn(a, b);
    return *(unsigned*)&h;
}

// ============================================================================
// fp16 tensor-core GEMM (A single fp16, W split hi+lo -> 2 MMA terms):
//   C[M,256] = op(A[M,256] @ W[256,256] + bias),  C fp16
// AF: A computed on the fly as relu(attr@Wc+bc) (edge MLP layer-1 fused)
// RELU epilogue; SC: per-row struct-scale from attr[:,1].
// Block 128x128, BK=64, 8 warps (2m x 4n), warp tile 64x32.
// ============================================================================
#define PITCH 72
#define SMEM_BYTES (3 * 128 * PITCH * 2)   // 55296

template <bool AF, bool RELU, bool SC>
__global__ __launch_bounds__(256, 2) void k_mma(
    const __half* __restrict__ A, const float* __restrict__ attr,
    const __half* __restrict__ Wsp,  // [hi 65536][lo 65536], [n][k]
    const float* __restrict__ bias, const float* __restrict__ sscale,
    __half* __restrict__ C, int M) {
    extern __shared__ __half smh[];
    __half* sA = smh;                       // 9216 elems
    const uint32_t sbase = smem_to_u32(smh);

    int tid = threadIdx.x;
    int lane = tid & 31, wid = tid >> 5;
    int wm = wid >> 2, wn = wid & 3;        // 2m x 4n; warp tile 64x32
    int row0 = blockIdx.x * 128;
    int n0 = blockIdx.y * 128;
    const __half* Whi = Wsp;
    const __half* Wlo = Wsp + 65536;

    float acc[4][4][4];
#pragma unroll
    for (int mt = 0; mt < 4; mt++)
#pragma unroll
        for (int nt = 0; nt < 4; nt++)
#pragma unroll
            for (int j = 0; j < 4; j++) acc[mt][nt][j] = 0.f;

    for (int c = 0; c < 4; c++) {
        int k0 = c * 64;
        int hr = tid >> 1, kh = (tid & 1) * 32;
        // ---- stage B chunk [128 n][64 k] hi+lo via cp.async ----
        {
            const __half* ph = Whi + (size_t)(n0 + hr) * 256 + k0 + kh;
            const __half* pl = Wlo + (size_t)(n0 + hr) * 256 + k0 + kh;
            uint32_t dbh = sbase + (9216 + hr * PITCH + kh) * 2;
            uint32_t dbl = sbase + (18432 + hr * PITCH + kh) * 2;
#pragma unroll
            for (int q = 0; q < 4; q++) {
                cpasync16(dbh + q * 16, ph + q * 8);
                cpasync16(dbl + q * 16, pl + q * 8);
            }
        }
        // ---- stage A chunk [128 m][64 k] fp16 ----
        if (AF) {
            float4 a = *(const float4*)(attr + (size_t)(row0 + hr) * 4);
#pragma unroll
            for (int j = 0; j < 16; j++) {
                int k = k0 + kh + 2 * j;
                float v0 = fmaxf(a.x * d_Wc[k] + a.y * d_Wc[256 + k] +
                                 a.z * d_Wc[512 + k] + a.w * d_Wc[768 + k] + d_bc[k], 0.f);
                float v1 = fmaxf(a.x * d_Wc[k + 1] + a.y * d_Wc[257 + k] +
                                 a.z * d_Wc[513 + k] + a.w * d_Wc[769 + k] + d_bc[k + 1], 0.f);
                *(unsigned*)&sA[hr * PITCH + kh + 2 * j] = pack2(v0, v1);
            }
        } else {
            int rc = min(row0 + hr, M - 1);   // clamp: garbage only affects rows >= M
            const __half* Ar = A + (size_t)rc * HH + k0 + kh;
            uint32_t da = sbase + (hr * PITCH + kh) * 2;
#pragma unroll
            for (int q = 0; q < 4; q++) cpasync16(da + q * 16, Ar + q * 8);
        }
        CP_COMMIT();
        CP_WAIT0();
        __syncthreads();

        // ---- compute: 4 k16-steps; 2 split-products each ----
#pragma unroll
        for (int ks = 0; ks < 64; ks += 16) {
            unsigned fA[4][4];
#pragma unroll
            for (int mt = 0; mt < 4; mt++) {
                int mrow = wm * 64 + mt * 16 + (lane & 15);
                uint32_t off = (uint32_t)(mrow * PITCH + ks + ((lane >> 4) << 3)) * 2;
                ldsm4(fA[mt], sbase + off);
            }
#pragma unroll
            for (int nt = 0; nt < 4; nt++) {
                int l = lane & 15;
                int nrow = wn * 32 + nt * 8 + (l & 7);
                uint32_t off = (uint32_t)(nrow * PITCH + ks + ((l & 8) ? 8 : 0)) * 2;
                unsigned fBh[2], fBl[2];
                ldsm2(fBh, sbase + 18432 + off);
                ldsm2(fBl, sbase + 36864 + off);
#pragma unroll
                for (int mt = 0; mt < 4; mt++) {
                    mma16816(acc[mt][nt], fA[mt], fBh);
                    mma16816(acc[mt][nt], fA[mt], fBl);
                }
            }
        }
        __syncthreads();
    }

    // ---- epilogue: bias / relu / struct-scale, fp16 stores ----
#pragma unroll
    for (int mt = 0; mt < 4; mt++) {
        int r1 = row0 + wm * 64 + mt * 16 + (lane >> 2);
        int r2 = r1 + 8;
        float s1 = 1.f, s2 = 1.f;
        if (SC) {
            float ssv = __ldg(sscale);
            s1 = (attr[(size_t)r1 * 4 + 1] > 0.f) ? ssv : 1.f;
            s2 = (attr[(size_t)r2 * 4 + 1] > 0.f) ? ssv : 1.f;
        }
#pragma unroll
        for (int nt = 0; nt < 4; nt++) {
            int col = n0 + wn * 32 + nt * 8 + 2 * (lane & 3);
            float2 b = *(const float2*)(bias + col);
            float v0 = acc[mt][nt][0] + b.x, v1 = acc[mt][nt][1] + b.y;
            float v2 = acc[mt][nt][2] + b.x, v3 = acc[mt][nt][3] + b.y;
            if (RELU) {
                v0 = fmaxf(v0, 0.f); v1 = fmaxf(v1, 0.f);
                v2 = fmaxf(v2, 0.f); v3 = fmaxf(v3, 0.f);
            }
            if (SC) { v0 *= s1; v1 *= s1; v2 *= s2; v3 *= s2; }
            if (r1 < M) *(__half2*)(C + (size_t)r1 * HH + col) = __floats2half2_rn(v0, v1);
            if (r2 < M) *(__half2*)(C + (size_t)r2 * HH + col) = __floats2half2_rn(v2, v3);
        }
    }
}

// ---------------- weight split/transpose: W[k][n] fp32 -> Whi/Wlo[n][k] fp16 ----
__global__ void k_wsplit(const float* __restrict__ eW2, const float* __restrict__ cW1,
                         const float* __restrict__ cW2) {
    int m = blockIdx.x >> 8;
    int n = blockIdx.x & 255;
    const float* W = (m == 0) ? eW2
                   : (m <= 3 ? cW1 + (size_t)(m - 1) * 65536 : cW2 + (size_t)(m - 4) * 65536);
    unsigned short* hi = d_wsplit + (size_t)m * 131072 + n * 256;
    unsigned short* lo = hi + 65536;
    for (int k = threadIdx.x; k < 256; k += 64) {
        float w = W[(size_t)k * 256 + n];
        __half h = __float2half_rn(w);
        float r = w - __half2float(h);
        hi[k] = __half_as_ushort(h);
        lo[k] = __half_as_ushort(__float2half_rn(r));
    }
}

// ---------------- small helpers ----------------
__global__ void k_zero_f(float* p, int n) {
    int i = blockIdx.x * blockDim.x + threadIdx.x;
    if (i < n) p[i] = 0.f;
}
__global__ void k_zero_i(int* p, int n) {
    int i = blockIdx.x * blockDim.x + threadIdx.x;
    if (i < n) p[i] = 0;
}

__global__ void k_prep(const float* __restrict__ Wemb, const float* __restrict__ eb,
                       const float* __restrict__ W1, const float* __restrict__ b1,
                       const float* __restrict__ bio, const float* __restrict__ hW1,
                       const float* __restrict__ hb1) {
    int j = threadIdx.x;
    float wc0 = 0.f, wc1 = 0.f, wc2 = 0.f, wc3 = 0.f, bc = 0.f;
    for (int d = 0; d < HH; d++) {
        float w = W1[d * HH + j];
        wc0 += Wemb[0 * HH + d] * w;
        wc1 += Wemb[1 * HH + d] * w;
        wc2 += Wemb[2 * HH + d] * w;
        wc3 += Wemb[3 * HH + d] * w;
        bc  += eb[d] * w;
    }
    d_Wc[0 * HH + j] = wc0;
    d_Wc[1 * HH + j] = wc1;
    d_Wc[2 * HH + j] = wc2;
    d_Wc[3 * HH + j] = wc3;
    d_bc[j] = bc + b1[j];
    float bb = hb1[j];
    for (int k = 0; k < BIOD; k++) bb += bio[k] * hW1[(HH + k) * HH + j];
    d_biob[j] = bb;
}

// h[n] = node_emb_W[x[n]]  (fp16 out); 32 threads per node, 8 halves each
__global__ void k_node_emb(const int* __restrict__ x, const float* __restrict__ emb) {
    int idx = blockIdx.x * blockDim.x + threadIdx.x;
    int node = idx >> 5;
    int q = idx & 31;
    if (node >= NN) return;
    int xv = x[node];
    const float* src = emb + (size_t)xv * HH + q * 8;
    float4 a = *(const float4*)src;
    float4 b = *(const float4*)(src + 4);
    uint4 o;
    o.x = pack2(a.x, a.y); o.y = pack2(a.z, a.w);
    o.z = pack2(b.x, b.y); o.w = pack2(b.z, b.w);
    *(uint4*)(d_h + (size_t)node * HH + q * 8) = o;
}

// ---------------- CSR build over dst ----------------
__global__ void k_deg(const int* __restrict__ ei) {
    int e = blockIdx.x * blockDim.x + threadIdx.x;
    if (e < EE) atomicAdd(&d_deg[ei[EE + e]], 1);
}
__global__ void k_scan() {
    __shared__ int s[1024];
    int tid = threadIdx.x;
    const int chunk = (NN + 1023) / 1024;
    int beg = tid * chunk;
    int end = min(beg + chunk, NN);
    int sum = 0;
    for (int i = beg; i < end; i++) sum += d_deg[i];
    s[tid] = sum;
    __syncthreads();
    for (int off = 1; off < 1024; off <<= 1) {
        int v = (tid >= off) ? s[tid - off] : 0;
        __syncthreads();
        s[tid] += v;
        __syncthreads();
    }
    int run = (tid > 0) ? s[tid - 1] : 0;
    for (int i = beg; i < end; i++) {
        d_rowptr[i] = run;
        run += d_deg[i];
    }
    if (tid == 1023) d_rowptr[NN] = s[1023];
}
__global__ void k_cursor() {
    int i = blockIdx.x * blockDim.x + threadIdx.x;
    if (i < NN) d_cursor[i] = d_rowptr[i];
}
__global__ void k_fill(const int* __restrict__ ei) {
    int e = blockIdx.x * blockDim.x + threadIdx.x;
    if (e < EE) {
        int dst = ei[EE + e];
        int p = atomicAdd(&d_cursor[dst], 1);
        d_csr[p] = e;
    }
}
__global__ void k_cnt(const int* __restrict__ batch) {
    int i = blockIdx.x * blockDim.x + threadIdx.x;
    if (i < NN) atomicAdd(&d_gcnt[batch[i]], 1.f);
}

// z = (1+eps_l)*h + sum relu(h[src] + e[eid]); fp16 in/out, fp32 accum
__global__ void k_aggregate(const int* __restrict__ ei, const float* __restrict__ conv_eps, int l) {
    int tid = threadIdx.x;
    int node = blockIdx.x * 8 + (tid >> 5);
    int q = tid & 31;   // 8 halves per thread
    if (node >= NN) return;
    float eps1 = 1.f + conv_eps[l];
    float acc[8];
#pragma unroll
    for (int j = 0; j < 8; j++) acc[j] = 0.f;
    int pbeg = d_rowptr[node];
    int pend = d_rowptr[node + 1];
    for (int p = pbeg; p < pend; p++) {
        int eid = d_csr[p];
        int src = ei[eid];
        uint4 hv = *(const uint4*)(d_h + (size_t)src * HH + q * 8);
        uint4 ev = *(const uint4*)(d_e + (size_t)eid * HH + q * 8);
        const unsigned* hw = &hv.x;
        const unsigned* ew = &ev.x;
#pragma unroll
        for (int j = 0; j < 4; j++) {
            float2 hf = __half22float2(*(const __half2*)&hw[j]);
            float2 ef = __half22float2(*(const __half2*)&ew[j]);
            acc[2 * j]     += fmaxf(hf.x + ef.x, 0.f);
            acc[2 * j + 1] += fmaxf(hf.y + ef.y, 0.f);
        }
    }
    uint4 hs = *(const uint4*)(d_h + (size_t)node * HH + q * 8);
    const unsigned* hw = &hs.x;
    uint4 o;
    unsigned* ow = &o.x;
#pragma unroll
    for (int j = 0; j < 4; j++) {
        float2 hf = __half22float2(*(const __half2*)&hw[j]);
        ow[j] = pack2(eps1 * hf.x + acc[2 * j], eps1 * hf.y + acc[2 * j + 1]);
    }
    *(uint4*)(d_z + (size_t)node * HH + q * 8) = o;
}

// fused segment sum (+ optional sum of squares) over sorted batch
template <bool SQ>
__global__ void k_seg2(const __half* __restrict__ src, float* __restrict__ s1out,
                       float* __restrict__ s2out, const int* __restrict__ batch) {
    int n0 = blockIdx.x * 16;
    int d = threadIdx.x;
    float a1 = 0.f, a2 = 0.f;
    int cur = -1;
#pragma unroll 4
    for (int i = 0; i < 16; i++) {
        int node = n0 + i;
        if (node >= NN) break;
        int g = batch[node];
        if (g != cur) {
            if (cur >= 0) {
                atomicAdd(&s1out[cur * HH + d], a1);
                if (SQ) atomicAdd(&s2out[cur * HH + d], a2);
            }
            cur = g;
            a1 = 0.f; a2 = 0.f;
        }
        float v = __half2float(src[(size_t)node * HH + d]);
        a1 += v;
        if (SQ) a2 += v * v;
    }
    if (cur >= 0) {
        atomicAdd(&s1out[cur * HH + d], a1);
        if (SQ) atomicAdd(&s2out[cur * HH + d], a2);
    }
}

// finalize mean + variance:  var = s2/n - alpha*(2-alpha)*mean^2
__global__ void k_fin2(const float* __restrict__ alpha_l) {
    int i = blockIdx.x * blockDim.x + threadIdx.x;
    if (i >= GG * HH) return;
    float n = fmaxf(d_gcnt[i >> 8], 1.f);
    float m = d_gsum[i] / n;
    d_gmean[i] = m;
    float a = alpha_l[i & 255];
    d_gvar[i] = d_gsumsq[i] / n - a * (2.f - a) * m * m;
}

// pool finalize: gpool = gsum / n
__global__ void k_finpool() {
    int i = blockIdx.x * blockDim.x + threadIdx.x;
    if (i >= GG * HH) return;
    float n = fmaxf(d_gcnt[i >> 8], 1.f);
    d_gpool[i] = d_gsum[i] / n;
}

// h = gamma*(h - alpha*mean)*rsqrt(var+eps) + beta   (fp16 in/out)
__global__ void k_norm(const int* __restrict__ batch, const float* __restrict__ gamma,
                       const float* __restrict__ beta, const float* __restrict__ alpha, int l) {
    int idx = blockIdx.x * blockDim.x + threadIdx.x;
    int node = idx >> 5;
    int q = idx & 31;   // 8 halves
    if (node >= NN) return;
    int g = batch[node];
    uint4 hv = *(const uint4*)(d_h + (size_t)node * HH + q * 8);
    const unsigned* hw = &hv.x;
    uint4 o;
    unsigned* ow = &o.x;
#pragma unroll
    for (int j = 0; j < 4; j++) {
        int ch = q * 8 + 2 * j;
        float2 hf = __half22float2(*(const __half2*)&hw[j]);
        float2 m = *(const float2*)(d_gmean + g * HH + ch);
        float2 v = *(const float2*)(d_gvar + g * HH + ch);
        float2 ga = *(const float2*)(gamma + l * HH + ch);
        float2 be = *(const float2*)(beta + l * HH + ch);
        float2 al = *(const float2*)(alpha + l * HH + ch);
        float o0 = ga.x * (hf.x - al.x * m.x) * rsqrtf(v.x + GEPS) + be.x;
        float o1 = ga.y * (hf.y - al.y * m.y) * rsqrtf(v.y + GEPS) + be.y;
        ow[j] = pack2(o0, o1);
    }
    *(uint4*)(d_h + (size_t)node * HH + q * 8) = o;
}

__global__ void k_head(const float* __restrict__ hW1, const float* __restrict__ hW2,
                       const float* __restrict__ hb2, float* __restrict__ out) {
    int g = blockIdx.x;
    int j = threadIdx.x;
    __shared__ float red[256];
    float acc = d_biob[j];
    const float* grow = d_gpool + g * HH;
    for (int k = 0; k < HH; k++) acc += grow[k] * hW1[k * HH + j];
    red[j] = fmaxf(acc, 0.f) * hW2[j];
    __syncthreads();
    for (int off = 128; off > 0; off >>= 1) {
        if (j < off) red[j] += red[j + off];
        __syncthreads();
    }
    if (j == 0) out[g] = red[0] + hb2[0];
}

// ---------------- launch ----------------
extern "C" void kernel_launch(void* const* d_in, const int* in_sizes, int n_in,
                              void* d_out, int out_size) {
    const int* x = (const int*)d_in[0];
    const int* ei = (const int*)d_in[1];
    const float* edge_attr = (const float*)d_in[2];
    const int* batch = (const int*)d_in[3];
    const float* node_emb_W = (const float*)d_in[4];
    const float* edge_emb_W = (const float*)d_in[5];
    const float* edge_emb_b = (const float*)d_in[6];
    const float* edge_mlp_W1 = (const float*)d_in[7];
    const float* edge_mlp_b1 = (const float*)d_in[8];
    const float* edge_mlp_W2 = (const float*)d_in[9];
    const float* edge_mlp_b2 = (const float*)d_in[10];
    const float* struct_scale = (const float*)d_in[11];
    const float* conv_W1 = (const float*)d_in[12];
    const float* conv_b1 = (const float*)d_in[13];
    const float* conv_W2 = (const float*)d_in[14];
    const float* conv_b2 = (const float*)d_in[15];
    const float* conv_eps = (const float*)d_in[16];
    const float* norm_gamma = (const float*)d_in[17];
    const float* norm_beta = (const float*)d_in[18];
    const float* norm_alpha = (const float*)d_in[19];
    const float* mean_bio = (const float*)d_in[20];
    const float* head_W1 = (const float*)d_in[21];
    const float* head_b1 = (const float*)d_in[22];
    const float* head_W2 = (const float*)d_in[23];
    const float* head_b2 = (const float*)d_in[24];
    float* out = (float*)d_out;
    (void)in_sizes; (void)n_in; (void)out_size;

    float *g_gsum, *g_gsumsq;
    __half *g_e, *g_z, *g_t, *g_h;
    int* g_deg;
    unsigned short* g_wsp;
    cudaGetSymbolAddress((void**)&g_gsum, d_gsum);
    cudaGetSymbolAddress((void**)&g_gsumsq, d_gsumsq);
    cudaGetSymbolAddress((void**)&g_e, d_e);
    cudaGetSymbolAddress((void**)&g_z, d_z);
    cudaGetSymbolAddress((void**)&g_t, d_t);
    cudaGetSymbolAddress((void**)&g_h, d_h);
    cudaGetSymbolAddress((void**)&g_deg, d_deg);
    cudaGetSymbolAddress((void**)&g_wsp, d_wsplit);
    float* g_gcnt;
    cudaGetSymbolAddress((void**)&g_gcnt, d_gcnt);

    cudaFuncSetAttribute(k_mma<true, false, true>,
                         cudaFuncAttributeMaxDynamicSharedMemorySize, SMEM_BYTES);
    cudaFuncSetAttribute(k_mma<false, true, false>,
                         cudaFuncAttributeMaxDynamicSharedMemorySize, SMEM_BYTES);
    cudaFuncSetAttribute(k_mma<false, false, false>,
                         cudaFuncAttributeMaxDynamicSharedMemorySize, SMEM_BYTES);

    // 1. fold small weights; split/transpose big weights to fp16 hi/lo
    k_prep<<<1, 256>>>(edge_emb_W, edge_emb_b, edge_mlp_W1, edge_mlp_b1,
                       mean_bio, head_W1, head_b1);
    k_wsplit<<<7 * 256, 64>>>(edge_mlp_W2, conv_W1, conv_W2);
    // 2. node embedding (fp16)
    k_node_emb<<<(NN * 32 + 255) / 256, 256>>>(x, node_emb_W);
    // 3. edge features: e = (relu(attr@Wc+bc) @ W2 + b2) * struct  (fp16 out)
    k_mma<true, false, true><<<dim3(EE / 128, 2), 256, SMEM_BYTES>>>(
        nullptr, edge_attr, (const __half*)g_wsp, edge_mlp_b2, struct_scale, g_e, EE);
    // 4. CSR build
    k_zero_i<<<(NN + 255) / 256, 256>>>(g_deg, NN);
    k_deg<<<(EE + 255) / 256, 256>>>(ei);
    k_scan<<<1, 1024>>>();
    k_cursor<<<(NN + 255) / 256, 256>>>();
    k_fill<<<(EE + 255) / 256, 256>>>(ei);
    // 5. per-graph counts
    k_zero_f<<<1, 256>>>(g_gcnt, GG);
    k_cnt<<<(NN + 255) / 256, 256>>>(batch);

    const int mb = (NN + 127) / 128;
    for (int l = 0; l < 3; l++) {
        k_aggregate<<<(NN + 7) / 8, 256>>>(ei, conv_eps, l);
        k_mma<false, true, false><<<dim3(mb, 2), 256, SMEM_BYTES>>>(
            g_z, nullptr, (const __half*)(g_wsp + (size_t)(1 + l) * 131072),
            conv_b1 + l * HH, nullptr, g_t, NN);
        k_mma<false, false, false><<<dim3(mb, 2), 256, SMEM_BYTES>>>(
            g_t, nullptr, (const __half*)(g_wsp + (size_t)(4 + l) * 131072),
            conv_b2 + l * HH, nullptr, g_h, NN);
        // GraphNorm: one pass for sum + sumsq, finalize, normalize
        k_zero_f<<<(GG * HH + 255) / 256, 256>>>(g_gsum, GG * HH);
        k_zero_f<<<(GG * HH + 255) / 256, 256>>>(g_gsumsq, GG * HH);
        k_seg2<true><<<(NN + 15) / 16, 256>>>(g_h, g_gsum, g_gsumsq, batch);
        k_fin2<<<(GG * HH + 255) / 256, 256>>>(norm_alpha + l * HH);
        k_norm<<<(NN * 32 + 255) / 256, 256>>>(batch, norm_gamma, norm_beta, norm_alpha, l);
    }

    // 6. mean pool + head
    k_zero_f<<<(GG * HH + 255) / 256, 256>>>(g_gsum, GG * HH);
    k_seg2<false><<<(NN + 15) / 16, 256>>>(g_h, g_gsum, nullptr, batch);
    k_finpool<<<(GG * HH + 255) / 256, 256>>>();
    k_head<<<GG, 256>>>(head_W1, head_W2, head_b2, out);
}

// round 6
// speedup vs baseline: 2.6466x; 1.2148x over previous
#include <cuda_runtime.h>
#include <cuda_fp16.h>
#include <cstdint>

#define NN 100000
#define EE 400000
#define GG 256
#define HH 256
#define BIOD 512
#define GEPS 1e-5f

// ---------------- scratch (device globals) ----------------
static __device__ __half d_h[(size_t)NN * HH];
static __device__ __half d_z[(size_t)NN * HH];
static __device__ __half d_t[(size_t)NN * HH];
static __device__ __half d_e[(size_t)EE * HH];
static __device__ int    d_deg[NN];
static __device__ int    d_rowptr[NN + 1];
static __device__ int    d_cursor[NN];
static __device__ int    d_csr[EE];
static __device__ float  d_Wc[4 * HH];
static __device__ float  d_bc[HH];
static __device__ float  d_biob[HH];
static __device__ float  d_gsum[GG * HH];
static __device__ float  d_gsumsq[GG * HH];
static __device__ float  d_gvar[GG * HH];
static __device__ float  d_gmean[GG * HH];
static __device__ float  d_gcnt[GG];
static __device__ float  d_gpool[GG * HH];
// 7 weight matrices x 256x256 fp16, layout [mat][n][k], stride 131072 kept
static __device__ unsigned short d_wsplit[(size_t)7 * 2 * 65536];

// ---------------- asm helpers ----------------
__device__ __forceinline__ uint32_t smem_to_u32(const void* smem_ptr) {
    uint32_t addr;
    asm("{ .reg .u64 tmp; cvta.to.shared.u64 tmp, %1; cvt.u32.u64 %0, tmp; }"
        : "=r"(addr) : "l"(smem_ptr));
    return addr;
}
__device__ __forceinline__ void ldsm4(unsigned* r, uint32_t addr) {
    asm volatile("ldmatrix.sync.aligned.m8n8.x4.shared.b16 {%0,%1,%2,%3}, [%4];"
                 : "=r"(r[0]), "=r"(r[1]), "=r"(r[2]), "=r"(r[3]) : "r"(addr));
}
__device__ __forceinline__ void mma16816(float* d, const unsigned* a, const unsigned* b) {
    asm volatile(
        "mma.sync.aligned.m16n8k16.row.col.f32.f16.f16.f32 "
        "{%0,%1,%2,%3}, {%4,%5,%6,%7}, {%8,%9}, {%0,%1,%2,%3};"
        : "+f"(d[0]), "+f"(d[1]), "+f"(d[2]), "+f"(d[3])
        : "r"(a[0]), "r"(a[1]), "r"(a[2]), "r"(a[3]), "r"(b[0]), "r"(b[1]));
}
__device__ __forceinline__ void cpasync16(uint32_t dst, const void* src) {
    asm volatile("cp.async.ca.shared.global [%0], [%1], 16;" :: "r"(dst), "l"(src));
}
#define CP_COMMIT() asm volatile("cp.async.commit_group;" ::: "memory")
#define CP_WAIT(n)  asm volatile("cp.async.wait_group %0;" :: "n"(n) : "memory")

// pack 2 floats -> fp16x2 word
__device__ __forceinline__ unsigned pack2(float a, float b) {
    __half2 h = __floats2half2_rn(a, b);
    return *(unsigned*)&h;
}

// ============================================================================
// fp16 tensor-core GEMM (pure fp16 weights, 1 MMA term, double-buffered):
//   C[M,256] = op(A[M,256] @ W[256,256] + bias),  C fp16
// AF: A computed on the fly as relu(attr@Wc+bc) (edge MLP layer-1 fused)
// RELU epilogue; SC: per-row struct-scale from attr[:,1].
// Block 128x128, BK=64 x 4 chunks (2-stage pipeline), 8 warps (2m x 4n),
// warp tile 64x32. SMEM: A[2] + B[2] buffers, each 128x72 fp16.
// ============================================================================
#define PITCH 72
#define BUFH 9216                       // halves per buffer
#define SMEM_BYTES (4 * BUFH * 2)       // 73728

template <bool AF, bool RELU, bool SC>
__global__ __launch_bounds__(256, 2) void k_mma(
    const __half* __restrict__ A, const float* __restrict__ attr,
    const __half* __restrict__ W,    // [n][k] fp16
    const float* __restrict__ bias, const float* __restrict__ sscale,
    __half* __restrict__ C, int M) {
    extern __shared__ __half smh[];
    const uint32_t sbase = smem_to_u32(smh);

    int tid = threadIdx.x;
    int lane = tid & 31, wid = tid >> 5;
    int wm = wid >> 2, wn = wid & 3;        // 2m x 4n; warp tile 64x32
    int row0 = blockIdx.x * 128;
    int n0 = blockIdx.y * 128;

    float acc[4][4][4];
#pragma unroll
    for (int mt = 0; mt < 4; mt++)
#pragma unroll
        for (int nt = 0; nt < 4; nt++)
#pragma unroll
            for (int j = 0; j < 4; j++) acc[mt][nt][j] = 0.f;

    const int hr = tid >> 1, kh = (tid & 1) * 32;

    // stage chunk c into buffer buf
    auto stage = [&](int c, int buf) {
        int k0 = c * 64;
        // B chunk [128 n][64 k]
        {
            const __half* pb = W + (size_t)(n0 + hr) * 256 + k0 + kh;
            uint32_t db = sbase + (uint32_t)(2 * BUFH + buf * BUFH + hr * PITCH + kh) * 2;
#pragma unroll
            for (int q = 0; q < 4; q++) cpasync16(db + q * 16, pb + q * 8);
        }
        // A chunk [128 m][64 k]
        if (AF) {
            float4 a = *(const float4*)(attr + (size_t)(row0 + hr) * 4);
            __half* sA = smh + buf * BUFH;
#pragma unroll
            for (int j = 0; j < 16; j++) {
                int k = k0 + kh + 2 * j;
                float v0 = fmaxf(a.x * d_Wc[k] + a.y * d_Wc[256 + k] +
                                 a.z * d_Wc[512 + k] + a.w * d_Wc[768 + k] + d_bc[k], 0.f);
                float v1 = fmaxf(a.x * d_Wc[k + 1] + a.y * d_Wc[257 + k] +
                                 a.z * d_Wc[513 + k] + a.w * d_Wc[769 + k] + d_bc[k + 1], 0.f);
                *(unsigned*)&sA[hr * PITCH + kh + 2 * j] = pack2(v0, v1);
            }
        } else {
            int rc = min(row0 + hr, M - 1);   // clamp: garbage only affects rows >= M
            const __half* Ar = A + (size_t)rc * HH + k0 + kh;
            uint32_t da = sbase + (uint32_t)(buf * BUFH + hr * PITCH + kh) * 2;
#pragma unroll
            for (int q = 0; q < 4; q++) cpasync16(da + q * 16, Ar + q * 8);
        }
    };

    // prologue: stage chunk 0
    stage(0, 0);
    CP_COMMIT();

#pragma unroll
    for (int c = 0; c < 4; c++) {
        int buf = c & 1;
        __syncthreads();                 // protect buffer (c+1)&1 from in-flight readers
        if (c < 3) {
            stage(c + 1, buf ^ 1);
            CP_COMMIT();
            CP_WAIT(1);                  // chunk c's group done; c+1 may be in flight
        } else {
            CP_WAIT(0);
        }
        __syncthreads();

        uint32_t abase = sbase + (uint32_t)(buf * BUFH) * 2;
        uint32_t bbase = sbase + (uint32_t)(2 * BUFH + buf * BUFH) * 2;
        // ---- compute: 4 k16-steps; 6 LDSM + 16 MMA each ----
#pragma unroll
        for (int ks = 0; ks < 64; ks += 16) {
            unsigned fA[4][4];
#pragma unroll
            for (int mt = 0; mt < 4; mt++) {
                int mrow = wm * 64 + mt * 16 + (lane & 15);
                ldsm4(fA[mt], abase + (uint32_t)(mrow * PITCH + ks + ((lane >> 4) << 3)) * 2);
            }
#pragma unroll
            for (int p = 0; p < 2; p++) {
                // x4 covers nt=2p (regs 0,1) and nt=2p+1 (regs 2,3)
                int g = lane >> 3, j = lane & 7;
                int nrow = wn * 32 + p * 16 + (g >> 1) * 8 + j;
                int kk = ks + (g & 1) * 8;
                unsigned fB[4];
                ldsm4(fB, bbase + (uint32_t)(nrow * PITCH + kk) * 2);
#pragma unroll
                for (int mt = 0; mt < 4; mt++) {
                    mma16816(acc[mt][2 * p], fA[mt], fB);
                    mma16816(acc[mt][2 * p + 1], fA[mt], fB + 2);
                }
            }
        }
    }

    // ---- epilogue: bias / relu / struct-scale, fp16 stores ----
#pragma unroll
    for (int mt = 0; mt < 4; mt++) {
        int r1 = row0 + wm * 64 + mt * 16 + (lane >> 2);
        int r2 = r1 + 8;
        float s1 = 1.f, s2 = 1.f;
        if (SC) {
            float ssv = __ldg(sscale);
            s1 = (attr[(size_t)r1 * 4 + 1] > 0.f) ? ssv : 1.f;
            s2 = (attr[(size_t)r2 * 4 + 1] > 0.f) ? ssv : 1.f;
        }
#pragma unroll
        for (int nt = 0; nt < 4; nt++) {
            int col = n0 + wn * 32 + nt * 8 + 2 * (lane & 3);
            float2 b = *(const float2*)(bias + col);
            float v0 = acc[mt][nt][0] + b.x, v1 = acc[mt][nt][1] + b.y;
            float v2 = acc[mt][nt][2] + b.x, v3 = acc[mt][nt][3] + b.y;
            if (RELU) {
                v0 = fmaxf(v0, 0.f); v1 = fmaxf(v1, 0.f);
                v2 = fmaxf(v2, 0.f); v3 = fmaxf(v3, 0.f);
            }
            if (SC) { v0 *= s1; v1 *= s1; v2 *= s2; v3 *= s2; }
            if (r1 < M) *(__half2*)(C + (size_t)r1 * HH + col) = __floats2half2_rn(v0, v1);
            if (r2 < M) *(__half2*)(C + (size_t)r2 * HH + col) = __floats2half2_rn(v2, v3);
        }
    }
}

// ---------------- weight transpose: W[k][n] fp32 -> W[n][k] fp16 ----
__global__ void k_wsplit(const float* __restrict__ eW2, const float* __restrict__ cW1,
                         const float* __restrict__ cW2) {
    int m = blockIdx.x >> 8;
    int n = blockIdx.x & 255;
    const float* W = (m == 0) ? eW2
                   : (m <= 3 ? cW1 + (size_t)(m - 1) * 65536 : cW2 + (size_t)(m - 4) * 65536);
    unsigned short* hi = d_wsplit + (size_t)m * 131072 + n * 256;
    for (int k = threadIdx.x; k < 256; k += 64)
        hi[k] = __half_as_ushort(__float2half_rn(W[(size_t)k * 256 + n]));
}

// ---------------- small helpers ----------------
__global__ void k_zero_f(float* p, int n) {
    int i = blockIdx.x * blockDim.x + threadIdx.x;
    if (i < n) p[i] = 0.f;
}
__global__ void k_zero_i(int* p, int n) {
    int i = blockIdx.x * blockDim.x + threadIdx.x;
    if (i < n) p[i] = 0;
}

__global__ void k_prep(const float* __restrict__ Wemb, const float* __restrict__ eb,
                       const float* __restrict__ W1, const float* __restrict__ b1,
                       const float* __restrict__ bio, const float* __restrict__ hW1,
                       const float* __restrict__ hb1) {
    int j = threadIdx.x;
    float wc0 = 0.f, wc1 = 0.f, wc2 = 0.f, wc3 = 0.f, bc = 0.f;
    for (int d = 0; d < HH; d++) {
        float w = W1[d * HH + j];
        wc0 += Wemb[0 * HH + d] * w;
        wc1 += Wemb[1 * HH + d] * w;
        wc2 += Wemb[2 * HH + d] * w;
        wc3 += Wemb[3 * HH + d] * w;
        bc  += eb[d] * w;
    }
    d_Wc[0 * HH + j] = wc0;
    d_Wc[1 * HH + j] = wc1;
    d_Wc[2 * HH + j] = wc2;
    d_Wc[3 * HH + j] = wc3;
    d_bc[j] = bc + b1[j];
    float bb = hb1[j];
    for (int k = 0; k < BIOD; k++) bb += bio[k] * hW1[(HH + k) * HH + j];
    d_biob[j] = bb;
}

// h[n] = node_emb_W[x[n]]  (fp16 out); 32 threads per node, 8 halves each
__global__ void k_node_emb(const int* __restrict__ x, const float* __restrict__ emb) {
    int idx = blockIdx.x * blockDim.x + threadIdx.x;
    int node = idx >> 5;
    int q = idx & 31;
    if (node >= NN) return;
    int xv = x[node];
    const float* src = emb + (size_t)xv * HH + q * 8;
    float4 a = *(const float4*)src;
    float4 b = *(const float4*)(src + 4);
    uint4 o;
    o.x = pack2(a.x, a.y); o.y = pack2(a.z, a.w);
    o.z = pack2(b.x, b.y); o.w = pack2(b.z, b.w);
    *(uint4*)(d_h + (size_t)node * HH + q * 8) = o;
}

// ---------------- CSR build over dst ----------------
__global__ void k_deg(const int* __restrict__ ei) {
    int e = blockIdx.x * blockDim.x + threadIdx.x;
    if (e < EE) atomicAdd(&d_deg[ei[EE + e]], 1);
}
__global__ void k_scan() {
    __shared__ int s[1024];
    int tid = threadIdx.x;
    const int chunk = (NN + 1023) / 1024;
    int beg = tid * chunk;
    int end = min(beg + chunk, NN);
    int sum = 0;
    for (int i = beg; i < end; i++) sum += d_deg[i];
    s[tid] = sum;
    __syncthreads();
    for (int off = 1; off < 1024; off <<= 1) {
        int v = (tid >= off) ? s[tid - off] : 0;
        __syncthreads();
        s[tid] += v;
        __syncthreads();
    }
    int run = (tid > 0) ? s[tid - 1] : 0;
    for (int i = beg; i < end; i++) {
        d_rowptr[i] = run;
        run += d_deg[i];
    }
    if (tid == 1023) d_rowptr[NN] = s[1023];
}
__global__ void k_cursor() {
    int i = blockIdx.x * blockDim.x + threadIdx.x;
    if (i < NN) d_cursor[i] = d_rowptr[i];
}
__global__ void k_fill(const int* __restrict__ ei) {
    int e = blockIdx.x * blockDim.x + threadIdx.x;
    if (e < EE) {
        int dst = ei[EE + e];
        int p = atomicAdd(&d_cursor[dst], 1);
        d_csr[p] = e;
    }
}
__global__ void k_cnt(const int* __restrict__ batch) {
    int i = blockIdx.x * blockDim.x + threadIdx.x;
    if (i < NN) atomicAdd(&d_gcnt[batch[i]], 1.f);
}

// z = (1+eps_l)*h + sum relu(h[src] + e[eid]); fp16 in/out, fp32 accum
__global__ void k_aggregate(const int* __restrict__ ei, const float* __restrict__ conv_eps, int l) {
    int tid = threadIdx.x;
    int node = blockIdx.x * 8 + (tid >> 5);
    int q = tid & 31;   // 8 halves per thread
    if (node >= NN) return;
    float eps1 = 1.f + conv_eps[l];
    float acc[8];
#pragma unroll
    for (int j = 0; j < 8; j++) acc[j] = 0.f;
    int pbeg = d_rowptr[node];
    int pend = d_rowptr[node + 1];
    for (int p = pbeg; p < pend; p++) {
        int eid = d_csr[p];
        int src = ei[eid];
        uint4 hv = *(const uint4*)(d_h + (size_t)src * HH + q * 8);
        uint4 ev = *(const uint4*)(d_e + (size_t)eid * HH + q * 8);
        const unsigned* hw = &hv.x;
        const unsigned* ew = &ev.x;
#pragma unroll
        for (int j = 0; j < 4; j++) {
            float2 hf = __half22float2(*(const __half2*)&hw[j]);
            float2 ef = __half22float2(*(const __half2*)&ew[j]);
            acc[2 * j]     += fmaxf(hf.x + ef.x, 0.f);
            acc[2 * j + 1] += fmaxf(hf.y + ef.y, 0.f);
        }
    }
    uint4 hs = *(const uint4*)(d_h + (size_t)node * HH + q * 8);
    const unsigned* hw = &hs.x;
    uint4 o;
    unsigned* ow = &o.x;
#pragma unroll
    for (int j = 0; j < 4; j++) {
        float2 hf = __half22float2(*(const __half2*)&hw[j]);
        ow[j] = pack2(eps1 * hf.x + acc[2 * j], eps1 * hf.y + acc[2 * j + 1]);
    }
    *(uint4*)(d_z + (size_t)node * HH + q * 8) = o;
}

// fused segment sum (+ optional sum of squares) over sorted batch
template <bool SQ>
__global__ void k_seg2(const __half* __restrict__ src, float* __restrict__ s1out,
                       float* __restrict__ s2out, const int* __restrict__ batch) {
    int n0 = blockIdx.x * 16;
    int d = threadIdx.x;
    float a1 = 0.f, a2 = 0.f;
    int cur = -1;
#pragma unroll 4
    for (int i = 0; i < 16; i++) {
        int node = n0 + i;
        if (node >= NN) break;
        int g = batch[node];
        if (g != cur) {
            if (cur >= 0) {
                atomicAdd(&s1out[cur * HH + d], a1);
                if (SQ) atomicAdd(&s2out[cur * HH + d], a2);
            }
            cur = g;
            a1 = 0.f; a2 = 0.f;
        }
        float v = __half2float(src[(size_t)node * HH + d]);
        a1 += v;
        if (SQ) a2 += v * v;
    }
    if (cur >= 0) {
        atomicAdd(&s1out[cur * HH + d], a1);
        if (SQ) atomicAdd(&s2out[cur * HH + d], a2);
    }
}

// finalize mean + variance:  var = s2/n - alpha*(2-alpha)*mean^2
__global__ void k_fin2(const float* __restrict__ alpha_l) {
    int i = blockIdx.x * blockDim.x + threadIdx.x;
    if (i >= GG * HH) return;
    float n = fmaxf(d_gcnt[i >> 8], 1.f);
    float m = d_gsum[i] / n;
    d_gmean[i] = m;
    float a = alpha_l[i & 255];
    d_gvar[i] = d_gsumsq[i] / n - a * (2.f - a) * m * m;
}

// pool finalize: gpool = gsum / n
__global__ void k_finpool() {
    int i = blockIdx.x * blockDim.x + threadIdx.x;
    if (i >= GG * HH) return;
    float n = fmaxf(d_gcnt[i >> 8], 1.f);
    d_gpool[i] = d_gsum[i] / n;
}

// h = gamma*(h - alpha*mean)*rsqrt(var+eps) + beta   (fp16 in/out)
__global__ void k_norm(const int* __restrict__ batch, const float* __restrict__ gamma,
                       const float* __restrict__ beta, const float* __restrict__ alpha, int l) {
    int idx = blockIdx.x * blockDim.x + threadIdx.x;
    int node = idx >> 5;
    int q = idx & 31;   // 8 halves
    if (node >= NN) return;
    int g = batch[node];
    uint4 hv = *(const uint4*)(d_h + (size_t)node * HH + q * 8);
    const unsigned* hw = &hv.x;
    uint4 o;
    unsigned* ow = &o.x;
#pragma unroll
    for (int j = 0; j < 4; j++) {
        int ch = q * 8 + 2 * j;
        float2 hf = __half22float2(*(const __half2*)&hw[j]);
        float2 m = *(const float2*)(d_gmean + g * HH + ch);
        float2 v = *(const float2*)(d_gvar + g * HH + ch);
        float2 ga = *(const float2*)(gamma + l * HH + ch);
        float2 be = *(const float2*)(beta + l * HH + ch);
        float2 al = *(const float2*)(alpha + l * HH + ch);
        float o0 = ga.x * (hf.x - al.x * m.x) * rsqrtf(v.x + GEPS) + be.x;
        float o1 = ga.y * (hf.y - al.y * m.y) * rsqrtf(v.y + GEPS) + be.y;
        ow[j] = pack2(o0, o1);
    }
    *(uint4*)(d_h + (size_t)node * HH + q * 8) = o;
}

__global__ void k_head(const float* __restrict__ hW1, const float* __restrict__ hW2,
                       const float* __restrict__ hb2, float* __restrict__ out) {
    int g = blockIdx.x;
    int j = threadIdx.x;
    __shared__ float red[256];
    float acc = d_biob[j];
    const float* grow = d_gpool + g * HH;
    for (int k = 0; k < HH; k++) acc += grow[k] * hW1[k * HH + j];
    red[j] = fmaxf(acc, 0.f) * hW2[j];
    __syncthreads();
    for (int off = 128; off > 0; off >>= 1) {
        if (j < off) red[j] += red[j + off];
        __syncthreads();
    }
    if (j == 0) out[g] = red[0] + hb2[0];
}

// ---------------- launch ----------------
extern "C" void kernel_launch(void* const* d_in, const int* in_sizes, int n_in,
                              void* d_out, int out_size) {
    const int* x = (const int*)d_in[0];
    const int* ei = (const int*)d_in[1];
    const float* edge_attr = (const float*)d_in[2];
    const int* batch = (const int*)d_in[3];
    const float* node_emb_W = (const float*)d_in[4];
    const float* edge_emb_W = (const float*)d_in[5];
    const float* edge_emb_b = (const float*)d_in[6];
    const float* edge_mlp_W1 = (const float*)d_in[7];
    const float* edge_mlp_b1 = (const float*)d_in[8];
    const float* edge_mlp_W2 = (const float*)d_in[9];
    const float* edge_mlp_b2 = (const float*)d_in[10];
    const float* struct_scale = (const float*)d_in[11];
    const float* conv_W1 = (const float*)d_in[12];
    const float* conv_b1 = (const float*)d_in[13];
    const float* conv_W2 = (const float*)d_in[14];
    const float* conv_b2 = (const float*)d_in[15];
    const float* conv_eps = (const float*)d_in[16];
    const float* norm_gamma = (const float*)d_in[17];
    const float* norm_beta = (const float*)d_in[18];
    const float* norm_alpha = (const float*)d_in[19];
    const float* mean_bio = (const float*)d_in[20];
    const float* head_W1 = (const float*)d_in[21];
    const float* head_b1 = (const float*)d_in[22];
    const float* head_W2 = (const float*)d_in[23];
    const float* head_b2 = (const float*)d_in[24];
    float* out = (float*)d_out;
    (void)in_sizes; (void)n_in; (void)out_size;

    float *g_gsum, *g_gsumsq, *g_gcnt;
    __half *g_e, *g_z, *g_t, *g_h;
    int* g_deg;
    unsigned short* g_wsp;
    cudaGetSymbolAddress((void**)&g_gsum, d_gsum);
    cudaGetSymbolAddress((void**)&g_gsumsq, d_gsumsq);
    cudaGetSymbolAddress((void**)&g_gcnt, d_gcnt);
    cudaGetSymbolAddress((void**)&g_e, d_e);
    cudaGetSymbolAddress((void**)&g_z, d_z);
    cudaGetSymbolAddress((void**)&g_t, d_t);
    cudaGetSymbolAddress((void**)&g_h, d_h);
    cudaGetSymbolAddress((void**)&g_deg, d_deg);
    cudaGetSymbolAddress((void**)&g_wsp, d_wsplit);

    cudaFuncSetAttribute(k_mma<true, false, true>,
                         cudaFuncAttributeMaxDynamicSharedMemorySize, SMEM_BYTES);
    cudaFuncSetAttribute(k_mma<false, true, false>,
                         cudaFuncAttributeMaxDynamicSharedMemorySize, SMEM_BYTES);
    cudaFuncSetAttribute(k_mma<false, false, false>,
                         cudaFuncAttributeMaxDynamicSharedMemorySize, SMEM_BYTES);

    // 1. fold small weights; transpose big weights to fp16 [n][k]
    k_prep<<<1, 256>>>(edge_emb_W, edge_emb_b, edge_mlp_W1, edge_mlp_b1,
                       mean_bio, head_W1, head_b1);
    k_wsplit<<<7 * 256, 64>>>(edge_mlp_W2, conv_W1, conv_W2);
    // 2. node embedding (fp16)
    k_node_emb<<<(NN * 32 + 255) / 256, 256>>>(x, node_emb_W);
    // 3. edge features: e = (relu(attr@Wc+bc) @ W2 + b2) * struct  (fp16 out)
    k_mma<true, false, true><<<dim3(EE / 128, 2), 256, SMEM_BYTES>>>(
        nullptr, edge_attr, (const __half*)g_wsp, edge_mlp_b2, struct_scale, g_e, EE);
    // 4. CSR build
    k_zero_i<<<(NN + 255) / 256, 256>>>(g_deg, NN);
    k_deg<<<(EE + 255) / 256, 256>>>(ei);
    k_scan<<<1, 1024>>>();
    k_cursor<<<(NN + 255) / 256, 256>>>();
    k_fill<<<(EE + 255) / 256, 256>>>(ei);
    // 5. per-graph counts
    k_zero_f<<<1, 256>>>(g_gcnt, GG);
    k_cnt<<<(NN + 255) / 256, 256>>>(batch);

    const int mb = (NN + 127) / 128;
    for (int l = 0; l < 3; l++) {
        k_aggregate<<<(NN + 7) / 8, 256>>>(ei, conv_eps, l);
        k_mma<false, true, false><<<dim3(mb, 2), 256, SMEM_BYTES>>>(
            g_z, nullptr, (const __half*)(g_wsp + (size_t)(1 + l) * 131072),
            conv_b1 + l * HH, nullptr, g_t, NN);
        k_mma<false, false, false><<<dim3(mb, 2), 256, SMEM_BYTES>>>(
            g_t, nullptr, (const __half*)(g_wsp + (size_t)(4 + l) * 131072),
            conv_b2 + l * HH, nullptr, g_h, NN);
        // GraphNorm: one pass for sum + sumsq, finalize, normalize
        k_zero_f<<<(GG * HH + 255) / 256, 256>>>(g_gsum, GG * HH);
        k_zero_f<<<(GG * HH + 255) / 256, 256>>>(g_gsumsq, GG * HH);
        k_seg2<true><<<(NN + 15) / 16, 256>>>(g_h, g_gsum, g_gsumsq, batch);
        k_fin2<<<(GG * HH + 255) / 256, 256>>>(norm_alpha + l * HH);
        k_norm<<<(NN * 32 + 255) / 256, 256>>>(batch, norm_gamma, norm_beta, norm_alpha, l);
    }

    // 6. mean pool + head
    k_zero_f<<<(GG * HH + 255) / 256, 256>>>(g_gsum, GG * HH);
    k_seg2<false><<<(NN + 15) / 16, 256>>>(g_h, g_gsum, nullptr, batch);
    k_finpool<<<(GG * HH + 255) / 256, 256>>>();
    k_head<<<GG, 256>>>(head_W1, head_W2, head_b2, out);
}

// round 7
// speedup vs baseline: 3.0353x; 1.1469x over previous
#include <cuda_runtime.h>
#include <cuda_fp16.h>
#include <cstdint>

#define NN 100000
#define EE 400000
#define GG 256
#define HH 256
#define BIOD 512
#define GEPS 1e-5f

// ---------------- scratch (device globals) ----------------
static __device__ __half d_h[(size_t)NN * HH];
static __device__ __half d_z[(size_t)NN * HH];
static __device__ __half d_t[(size_t)NN * HH];
static __device__ __half d_e[(size_t)EE * HH];   // stored in CSR-slot order
static __device__ int    d_deg[NN];
static __device__ int    d_rowptr[NN + 1];
static __device__ int    d_cursor[NN];
static __device__ int    d_epos[EE];             // edge id -> CSR slot
static __device__ int    d_srcv[EE];             // CSR slot -> src node
static __device__ float  d_Wc[4 * HH];
static __device__ float  d_bc[HH];
static __device__ float  d_biob[HH];
static __device__ float  d_gsum[GG * HH];
static __device__ float  d_gsumsq[GG * HH];
static __device__ float  d_gvar[GG * HH];
static __device__ float  d_gmean[GG * HH];
static __device__ float  d_gcnt[GG];
static __device__ float  d_gpool[GG * HH];
// 7 weight matrices x 256x256 fp16, layout [mat][n][k], stride 131072 kept
static __device__ unsigned short d_wsplit[(size_t)7 * 2 * 65536];

// ---------------- asm helpers ----------------
__device__ __forceinline__ uint32_t smem_to_u32(const void* smem_ptr) {
    uint32_t addr;
    asm("{ .reg .u64 tmp; cvta.to.shared.u64 tmp, %1; cvt.u32.u64 %0, tmp; }"
        : "=r"(addr) : "l"(smem_ptr));
    return addr;
}
__device__ __forceinline__ void ldsm4(unsigned* r, uint32_t addr) {
    asm volatile("ldmatrix.sync.aligned.m8n8.x4.shared.b16 {%0,%1,%2,%3}, [%4];"
                 : "=r"(r[0]), "=r"(r[1]), "=r"(r[2]), "=r"(r[3]) : "r"(addr));
}
__device__ __forceinline__ void mma16816(float* d, const unsigned* a, const unsigned* b) {
    asm volatile(
        "mma.sync.aligned.m16n8k16.row.col.f32.f16.f16.f32 "
        "{%0,%1,%2,%3}, {%4,%5,%6,%7}, {%8,%9}, {%0,%1,%2,%3};"
        : "+f"(d[0]), "+f"(d[1]), "+f"(d[2]), "+f"(d[3])
        : "r"(a[0]), "r"(a[1]), "r"(a[2]), "r"(a[3]), "r"(b[0]), "r"(b[1]));
}
__device__ __forceinline__ void cpasync16(uint32_t dst, const void* src) {
    asm volatile("cp.async.ca.shared.global [%0], [%1], 16;" :: "r"(dst), "l"(src));
}
#define CP_COMMIT() asm volatile("cp.async.commit_group;" ::: "memory")
#define CP_WAIT(n)  asm volatile("cp.async.wait_group %0;" :: "n"(n) : "memory")

__device__ __forceinline__ unsigned pack2(float a, float b) {
    __half2 h = __floats2half2_rn(a, b);
    return *(unsigned*)&h;
}

// ============================================================================
// fp16 tensor-core GEMM:  C[M,256] = op(A[M,256] @ W[256,256] + bias), C fp16
// AF: A computed on the fly as relu(attr@Wc+bc); weights register-resident;
//     attr staged in SMEM; output rows stored permuted to CSR slot epos[row],
//     pre-scaled by struct-scale.
// RELU epilogue for conv layer-1.
// Block 128x128, BK=64 x 4 chunks (2-stage cp.async pipeline),
// 8 warps (2m x 4n), warp tile 64x32.
// ============================================================================
#define PITCH 72
#define BUFH 9216                          // halves per buffer
#define SMEM_BYTES (4 * BUFH * 2 + 2048)   // 4 buffers + staged attr

template <bool AF, bool RELU>
__global__ __launch_bounds__(256, 2) void k_mma(
    const __half* __restrict__ A, const float* __restrict__ attr,
    const __half* __restrict__ W,    // [n][k] fp16
    const float* __restrict__ bias, const float* __restrict__ sscale,
    __half* __restrict__ C, int M) {
    extern __shared__ __half smh[];
    const uint32_t sbase = smem_to_u32(smh);
    float* sattr = (float*)(smh + 4 * BUFH);

    int tid = threadIdx.x;
    int lane = tid & 31, wid = tid >> 5;
    int wm = wid >> 2, wn = wid & 3;        // 2m x 4n; warp tile 64x32
    int row0 = blockIdx.x * 128;
    int n0 = blockIdx.y * 128;

    if (AF) {
        if (tid < 128)
            *(float4*)(sattr + tid * 4) = *(const float4*)(attr + (size_t)(row0 + tid) * 4);
        __syncthreads();
    }

    float acc[4][4][4];
#pragma unroll
    for (int mt = 0; mt < 4; mt++)
#pragma unroll
        for (int nt = 0; nt < 4; nt++)
#pragma unroll
            for (int j = 0; j < 4; j++) acc[mt][nt][j] = 0.f;

    const int hr = tid >> 1, kh = (tid & 1) * 32;
    const int kp = tid >> 3, rg = tid & 7;   // AF staging layout

    auto stage = [&](int c, int buf) {
        int k0 = c * 64;
        // B chunk [128 n][64 k]
        {
            const __half* pb = W + (size_t)(n0 + hr) * 256 + k0 + kh;
            uint32_t db = sbase + (uint32_t)(2 * BUFH + buf * BUFH + hr * PITCH + kh) * 2;
#pragma unroll
            for (int q = 0; q < 4; q++) cpasync16(db + q * 16, pb + q * 8);
        }
        // A chunk [128 m][64 k]
        if (AF) {
            int k = k0 + 2 * kp;
            float2 w0 = *(const float2*)(d_Wc + k);
            float2 w1 = *(const float2*)(d_Wc + 256 + k);
            float2 w2 = *(const float2*)(d_Wc + 512 + k);
            float2 w3 = *(const float2*)(d_Wc + 768 + k);
            float2 bb = *(const float2*)(d_bc + k);
            __half* sA = smh + buf * BUFH;
#pragma unroll
            for (int i = 0; i < 16; i++) {
                int r = rg + 8 * i;
                float4 a = *(const float4*)(sattr + r * 4);
                float v0 = fmaxf(a.x * w0.x + a.y * w1.x + a.z * w2.x + a.w * w3.x + bb.x, 0.f);
                float v1 = fmaxf(a.x * w0.y + a.y * w1.y + a.z * w2.y + a.w * w3.y + bb.y, 0.f);
                *(unsigned*)&sA[r * PITCH + 2 * kp] = pack2(v0, v1);
            }
        } else {
            int rc = min(row0 + hr, M - 1);
            const __half* Ar = A + (size_t)rc * HH + k0 + kh;
            uint32_t da = sbase + (uint32_t)(buf * BUFH + hr * PITCH + kh) * 2;
#pragma unroll
            for (int q = 0; q < 4; q++) cpasync16(da + q * 16, Ar + q * 8);
        }
    };

    stage(0, 0);
    CP_COMMIT();

#pragma unroll
    for (int c = 0; c < 4; c++) {
        int buf = c & 1;
        __syncthreads();                 // prior readers of buf^1 done
        if (c < 3) {
            stage(c + 1, buf ^ 1);
            CP_COMMIT();
            CP_WAIT(1);
        } else {
            CP_WAIT(0);
        }
        __syncthreads();

        uint32_t abase = sbase + (uint32_t)(buf * BUFH) * 2;
        uint32_t bbase = sbase + (uint32_t)(2 * BUFH + buf * BUFH) * 2;
#pragma unroll
        for (int ks = 0; ks < 64; ks += 16) {
            unsigned fA[4][4];
#pragma unroll
            for (int mt = 0; mt < 4; mt++) {
                int mrow = wm * 64 + mt * 16 + (lane & 15);
                ldsm4(fA[mt], abase + (uint32_t)(mrow * PITCH + ks + ((lane >> 4) << 3)) * 2);
            }
#pragma unroll
            for (int p = 0; p < 2; p++) {
                int g = lane >> 3, j = lane & 7;
                int nrow = wn * 32 + p * 16 + (g >> 1) * 8 + j;
                int kk = ks + (g & 1) * 8;
                unsigned fB[4];
                ldsm4(fB, bbase + (uint32_t)(nrow * PITCH + kk) * 2);
#pragma unroll
                for (int mt = 0; mt < 4; mt++) {
                    mma16816(acc[mt][2 * p], fA[mt], fB);
                    mma16816(acc[mt][2 * p + 1], fA[mt], fB + 2);
                }
            }
        }
    }

    // ---- epilogue ----
#pragma unroll
    for (int mt = 0; mt < 4; mt++) {
        int lr1 = wm * 64 + mt * 16 + (lane >> 2);
        int lr2 = lr1 + 8;
        int r1 = row0 + lr1, r2 = row0 + lr2;
        float s1 = 1.f, s2 = 1.f;
        size_t o1, o2;
        if (AF) {
            float ssv = __ldg(sscale);
            s1 = (sattr[lr1 * 4 + 1] > 0.f) ? ssv : 1.f;
            s2 = (sattr[lr2 * 4 + 1] > 0.f) ? ssv : 1.f;
            o1 = (size_t)d_epos[r1] * HH;
            o2 = (size_t)d_epos[r2] * HH;
        } else {
            o1 = (size_t)r1 * HH;
            o2 = (size_t)r2 * HH;
        }
#pragma unroll
        for (int nt = 0; nt < 4; nt++) {
            int col = n0 + wn * 32 + nt * 8 + 2 * (lane & 3);
            float2 b = *(const float2*)(bias + col);
            float v0 = acc[mt][nt][0] + b.x, v1 = acc[mt][nt][1] + b.y;
            float v2 = acc[mt][nt][2] + b.x, v3 = acc[mt][nt][3] + b.y;
            if (RELU) {
                v0 = fmaxf(v0, 0.f); v1 = fmaxf(v1, 0.f);
                v2 = fmaxf(v2, 0.f); v3 = fmaxf(v3, 0.f);
            }
            if (AF) { v0 *= s1; v1 *= s1; v2 *= s2; v3 *= s2; }
            if (r1 < M) *(__half2*)(C + o1 + col) = __floats2half2_rn(v0, v1);
            if (r2 < M) *(__half2*)(C + o2 + col) = __floats2half2_rn(v2, v3);
        }
    }
}

// ---------------- weight transpose: W[k][n] fp32 -> W[n][k] fp16 ----
__global__ void k_wsplit(const float* __restrict__ eW2, const float* __restrict__ cW1,
                         const float* __restrict__ cW2) {
    int m = blockIdx.x >> 8;
    int n = blockIdx.x & 255;
    const float* W = (m == 0) ? eW2
                   : (m <= 3 ? cW1 + (size_t)(m - 1) * 65536 : cW2 + (size_t)(m - 4) * 65536);
    unsigned short* hi = d_wsplit + (size_t)m * 131072 + n * 256;
    for (int k = threadIdx.x; k < 256; k += 64)
        hi[k] = __half_as_ushort(__float2half_rn(W[(size_t)k * 256 + n]));
}

// ---------------- small helpers ----------------
__global__ void k_zero_f(float* p, int n) {
    int i = blockIdx.x * blockDim.x + threadIdx.x;
    if (i < n) p[i] = 0.f;
}
__global__ void k_zero_i(int* p, int n) {
    int i = blockIdx.x * blockDim.x + threadIdx.x;
    if (i < n) p[i] = 0;
}

__global__ void k_prep(const float* __restrict__ Wemb, const float* __restrict__ eb,
                       const float* __restrict__ W1, const float* __restrict__ b1,
                       const float* __restrict__ bio, const float* __restrict__ hW1,
                       const float* __restrict__ hb1) {
    int j = threadIdx.x;
    float wc0 = 0.f, wc1 = 0.f, wc2 = 0.f, wc3 = 0.f, bc = 0.f;
    for (int d = 0; d < HH; d++) {
        float w = W1[d * HH + j];
        wc0 += Wemb[0 * HH + d] * w;
        wc1 += Wemb[1 * HH + d] * w;
        wc2 += Wemb[2 * HH + d] * w;
        wc3 += Wemb[3 * HH + d] * w;
        bc  += eb[d] * w;
    }
    d_Wc[0 * HH + j] = wc0;
    d_Wc[1 * HH + j] = wc1;
    d_Wc[2 * HH + j] = wc2;
    d_Wc[3 * HH + j] = wc3;
    d_bc[j] = bc + b1[j];
    float bb = hb1[j];
    for (int k = 0; k < BIOD; k++) bb += bio[k] * hW1[(HH + k) * HH + j];
    d_biob[j] = bb;
}

// h[n] = node_emb_W[x[n]]  (fp16 out)
__global__ void k_node_emb(const int* __restrict__ x, const float* __restrict__ emb) {
    int idx = blockIdx.x * blockDim.x + threadIdx.x;
    int node = idx >> 5;
    int q = idx & 31;
    if (node >= NN) return;
    int xv = x[node];
    const float* src = emb + (size_t)xv * HH + q * 8;
    float4 a = *(const float4*)src;
    float4 b = *(const float4*)(src + 4);
    uint4 o;
    o.x = pack2(a.x, a.y); o.y = pack2(a.z, a.w);
    o.z = pack2(b.x, b.y); o.w = pack2(b.z, b.w);
    *(uint4*)(d_h + (size_t)node * HH + q * 8) = o;
}

// ---------------- CSR build over dst ----------------
__global__ void k_deg(const int* __restrict__ ei) {
    int e = blockIdx.x * blockDim.x + threadIdx.x;
    if (e < EE) atomicAdd(&d_deg[ei[EE + e]], 1);
}
__global__ void k_scan() {
    __shared__ int s[1024];
    int tid = threadIdx.x;
    const int chunk = (NN + 1023) / 1024;
    int beg = tid * chunk;
    int end = min(beg + chunk, NN);
    int sum = 0;
    for (int i = beg; i < end; i++) sum += d_deg[i];
    s[tid] = sum;
    __syncthreads();
    for (int off = 1; off < 1024; off <<= 1) {
        int v = (tid >= off) ? s[tid - off] : 0;
        __syncthreads();
        s[tid] += v;
        __syncthreads();
    }
    int run = (tid > 0) ? s[tid - 1] : 0;
    for (int i = beg; i < end; i++) {
        d_rowptr[i] = run;
        run += d_deg[i];
    }
    if (tid == 1023) d_rowptr[NN] = s[1023];
}
__global__ void k_cursor() {
    int i = blockIdx.x * blockDim.x + threadIdx.x;
    if (i < NN) d_cursor[i] = d_rowptr[i];
}
__global__ void k_fill(const int* __restrict__ ei) {
    int e = blockIdx.x * blockDim.x + threadIdx.x;
    if (e < EE) {
        int dst = ei[EE + e];
        int p = atomicAdd(&d_cursor[dst], 1);
        d_epos[e] = p;
        d_srcv[p] = ei[e];
    }
}
__global__ void k_cnt(const int* __restrict__ batch) {
    int i = blockIdx.x * blockDim.x + threadIdx.x;
    if (i < NN) atomicAdd(&d_gcnt[batch[i]], 1.f);
}

// z = (1+eps_l)*h + sum_p relu(h[srcv[p]] + e[p]); e is slot-ordered (sequential)
__global__ void k_aggregate(const float* __restrict__ conv_eps, int l) {
    int tid = threadIdx.x;
    int node = blockIdx.x * 8 + (tid >> 5);
    int q = tid & 31;   // 8 halves per thread
    if (node >= NN) return;
    float eps1 = 1.f + conv_eps[l];
    float acc[8];
#pragma unroll
    for (int j = 0; j < 8; j++) acc[j] = 0.f;
    int pbeg = d_rowptr[node];
    int pend = d_rowptr[node + 1];
    int p = pbeg;
    for (; p + 1 < pend; p += 2) {
        int s0 = d_srcv[p], s1 = d_srcv[p + 1];
        uint4 h0 = *(const uint4*)(d_h + (size_t)s0 * HH + q * 8);
        uint4 e0 = *(const uint4*)(d_e + (size_t)p * HH + q * 8);
        uint4 h1 = *(const uint4*)(d_h + (size_t)s1 * HH + q * 8);
        uint4 e1 = *(const uint4*)(d_e + (size_t)(p + 1) * HH + q * 8);
        const unsigned *hw0 = &h0.x, *ew0 = &e0.x, *hw1 = &h1.x, *ew1 = &e1.x;
#pragma unroll
        for (int j = 0; j < 4; j++) {
            float2 a = __half22float2(*(const __half2*)&hw0[j]);
            float2 b = __half22float2(*(const __half2*)&ew0[j]);
            float2 c = __half22float2(*(const __half2*)&hw1[j]);
            float2 d = __half22float2(*(const __half2*)&ew1[j]);
            acc[2 * j]     += fmaxf(a.x + b.x, 0.f) + fmaxf(c.x + d.x, 0.f);
            acc[2 * j + 1] += fmaxf(a.y + b.y, 0.f) + fmaxf(c.y + d.y, 0.f);
        }
    }
    if (p < pend) {
        int s0 = d_srcv[p];
        uint4 h0 = *(const uint4*)(d_h + (size_t)s0 * HH + q * 8);
        uint4 e0 = *(const uint4*)(d_e + (size_t)p * HH + q * 8);
        const unsigned *hw0 = &h0.x, *ew0 = &e0.x;
#pragma unroll
        for (int j = 0; j < 4; j++) {
            float2 a = __half22float2(*(const __half2*)&hw0[j]);
            float2 b = __half22float2(*(const __half2*)&ew0[j]);
            acc[2 * j]     += fmaxf(a.x + b.x, 0.f);
            acc[2 * j + 1] += fmaxf(a.y + b.y, 0.f);
        }
    }
    uint4 hs = *(const uint4*)(d_h + (size_t)node * HH + q * 8);
    const unsigned* hw = &hs.x;
    uint4 o;
    unsigned* ow = &o.x;
#pragma unroll
    for (int j = 0; j < 4; j++) {
        float2 hf = __half22float2(*(const __half2*)&hw[j]);
        ow[j] = pack2(eps1 * hf.x + acc[2 * j], eps1 * hf.y + acc[2 * j + 1]);
    }
    *(uint4*)(d_z + (size_t)node * HH + q * 8) = o;
}

// fused segment sum (+ optional sum of squares) over sorted batch
template <bool SQ>
__global__ void k_seg2(const __half* __restrict__ src, float* __restrict__ s1out,
                       float* __restrict__ s2out, const int* __restrict__ batch) {
    int n0 = blockIdx.x * 16;
    int d = threadIdx.x;
    float a1 = 0.f, a2 = 0.f;
    int cur = -1;
#pragma unroll 4
    for (int i = 0; i < 16; i++) {
        int node = n0 + i;
        if (node >= NN) break;
        int g = batch[node];
        if (g != cur) {
            if (cur >= 0) {
                atomicAdd(&s1out[cur * HH + d], a1);
                if (SQ) atomicAdd(&s2out[cur * HH + d], a2);
            }
            cur = g;
            a1 = 0.f; a2 = 0.f;
        }
        float v = __half2float(src[(size_t)node * HH + d]);
        a1 += v;
        if (SQ) a2 += v * v;
    }
    if (cur >= 0) {
        atomicAdd(&s1out[cur * HH + d], a1);
        if (SQ) atomicAdd(&s2out[cur * HH + d], a2);
    }
}

// finalize mean + variance:  var = s2/n - alpha*(2-alpha)*mean^2
__global__ void k_fin2(const float* __restrict__ alpha_l) {
    int i = blockIdx.x * blockDim.x + threadIdx.x;
    if (i >= GG * HH) return;
    float n = fmaxf(d_gcnt[i >> 8], 1.f);
    float m = d_gsum[i] / n;
    d_gmean[i] = m;
    float a = alpha_l[i & 255];
    d_gvar[i] = d_gsumsq[i] / n - a * (2.f - a) * m * m;
}

// pool finalize: gpool = gsum / n
__global__ void k_finpool() {
    int i = blockIdx.x * blockDim.x + threadIdx.x;
    if (i >= GG * HH) return;
    float n = fmaxf(d_gcnt[i >> 8], 1.f);
    d_gpool[i] = d_gsum[i] / n;
}

// h = gamma*(h - alpha*mean)*rsqrt(var+eps) + beta   (fp16 in/out)
__global__ void k_norm(const int* __restrict__ batch, const float* __restrict__ gamma,
                       const float* __restrict__ beta, const float* __restrict__ alpha, int l) {
    int idx = blockIdx.x * blockDim.x + threadIdx.x;
    int node = idx >> 5;
    int q = idx & 31;   // 8 halves
    if (node >= NN) return;
    int g = batch[node];
    uint4 hv = *(const uint4*)(d_h + (size_t)node * HH + q * 8);
    const unsigned* hw = &hv.x;
    uint4 o;
    unsigned* ow = &o.x;
#pragma unroll
    for (int j = 0; j < 4; j++) {
        int ch = q * 8 + 2 * j;
        float2 hf = __half22float2(*(const __half2*)&hw[j]);
        float2 m = *(const float2*)(d_gmean + g * HH + ch);
        float2 v = *(const float2*)(d_gvar + g * HH + ch);
        float2 ga = *(const float2*)(gamma + l * HH + ch);
        float2 be = *(const float2*)(beta + l * HH + ch);
        float2 al = *(const float2*)(alpha + l * HH + ch);
        float o0 = ga.x * (hf.x - al.x * m.x) * rsqrtf(v.x + GEPS) + be.x;
        float o1 = ga.y * (hf.y - al.y * m.y) * rsqrtf(v.y + GEPS) + be.y;
        ow[j] = pack2(o0, o1);
    }
    *(uint4*)(d_h + (size_t)node * HH + q * 8) = o;
}

__global__ void k_head(const float* __restrict__ hW1, const float* __restrict__ hW2,
                       const float* __restrict__ hb2, float* __restrict__ out) {
    int g = blockIdx.x;
    int j = threadIdx.x;
    __shared__ float red[256];
    float acc = d_biob[j];
    const float* grow = d_gpool + g * HH;
    for (int k = 0; k < HH; k++) acc += grow[k] * hW1[k * HH + j];
    red[j] = fmaxf(acc, 0.f) * hW2[j];
    __syncthreads();
    for (int off = 128; off > 0; off >>= 1) {
        if (j < off) red[j] += red[j + off];
        __syncthreads();
    }
    if (j == 0) out[g] = red[0] + hb2[0];
}

// ---------------- launch ----------------
extern "C" void kernel_launch(void* const* d_in, const int* in_sizes, int n_in,
                              void* d_out, int out_size) {
    const int* x = (const int*)d_in[0];
    const int* ei = (const int*)d_in[1];
    const float* edge_attr = (const float*)d_in[2];
    const int* batch = (const int*)d_in[3];
    const float* node_emb_W = (const float*)d_in[4];
    const float* edge_emb_W = (const float*)d_in[5];
    const float* edge_emb_b = (const float*)d_in[6];
    const float* edge_mlp_W1 = (const float*)d_in[7];
    const float* edge_mlp_b1 = (const float*)d_in[8];
    const float* edge_mlp_W2 = (const float*)d_in[9];
    const float* edge_mlp_b2 = (const float*)d_in[10];
    const float* struct_scale = (const float*)d_in[11];
    const float* conv_W1 = (const float*)d_in[12];
    const float* conv_b1 = (const float*)d_in[13];
    const float* conv_W2 = (const float*)d_in[14];
    const float* conv_b2 = (const float*)d_in[15];
    const float* conv_eps = (const float*)d_in[16];
    const float* norm_gamma = (const float*)d_in[17];
    const float* norm_beta = (const float*)d_in[18];
    const float* norm_alpha = (const float*)d_in[19];
    const float* mean_bio = (const float*)d_in[20];
    const float* head_W1 = (const float*)d_in[21];
    const float* head_b1 = (const float*)d_in[22];
    const float* head_W2 = (const float*)d_in[23];
    const float* head_b2 = (const float*)d_in[24];
    float* out = (float*)d_out;
    (void)in_sizes; (void)n_in; (void)out_size;

    float *g_gsum, *g_gsumsq, *g_gcnt;
    __half *g_e, *g_z, *g_t, *g_h;
    int* g_deg;
    unsigned short* g_wsp;
    cudaGetSymbolAddress((void**)&g_gsum, d_gsum);
    cudaGetSymbolAddress((void**)&g_gsumsq, d_gsumsq);
    cudaGetSymbolAddress((void**)&g_gcnt, d_gcnt);
    cudaGetSymbolAddress((void**)&g_e, d_e);
    cudaGetSymbolAddress((void**)&g_z, d_z);
    cudaGetSymbolAddress((void**)&g_t, d_t);
    cudaGetSymbolAddress((void**)&g_h, d_h);
    cudaGetSymbolAddress((void**)&g_deg, d_deg);
    cudaGetSymbolAddress((void**)&g_wsp, d_wsplit);

    cudaFuncSetAttribute(k_mma<true, false>,
                         cudaFuncAttributeMaxDynamicSharedMemorySize, SMEM_BYTES);
    cudaFuncSetAttribute(k_mma<false, true>,
                         cudaFuncAttributeMaxDynamicSharedMemorySize, SMEM_BYTES);
    cudaFuncSetAttribute(k_mma<false, false>,
                         cudaFuncAttributeMaxDynamicSharedMemorySize, SMEM_BYTES);

    // 1. fold small weights; transpose big weights to fp16 [n][k]
    k_prep<<<1, 256>>>(edge_emb_W, edge_emb_b, edge_mlp_W1, edge_mlp_b1,
                       mean_bio, head_W1, head_b1);
    k_wsplit<<<7 * 256, 64>>>(edge_mlp_W2, conv_W1, conv_W2);
    // 2. node embedding (fp16)
    k_node_emb<<<(NN * 32 + 255) / 256, 256>>>(x, node_emb_W);
    // 3. CSR build (before edge GEMM: epos needed for permuted store)
    k_zero_i<<<(NN + 255) / 256, 256>>>(g_deg, NN);
    k_deg<<<(EE + 255) / 256, 256>>>(ei);
    k_scan<<<1, 1024>>>();
    k_cursor<<<(NN + 255) / 256, 256>>>();
    k_fill<<<(EE + 255) / 256, 256>>>(ei);
    // 4. edge features: e = (relu(attr@Wc+bc) @ W2 + b2) * struct, stored to CSR slots
    k_mma<true, false><<<dim3(EE / 128, 2), 256, SMEM_BYTES>>>(
        nullptr, edge_attr, (const __half*)g_wsp, edge_mlp_b2, struct_scale, g_e, EE);
    // 5. per-graph counts
    k_zero_f<<<1, 256>>>(g_gcnt, GG);
    k_cnt<<<(NN + 255) / 256, 256>>>(batch);

    const int mb = (NN + 127) / 128;
    for (int l = 0; l < 3; l++) {
        k_aggregate<<<(NN + 7) / 8, 256>>>(conv_eps, l);
        k_mma<false, true><<<dim3(mb, 2), 256, SMEM_BYTES>>>(
            g_z, nullptr, (const __half*)(g_wsp + (size_t)(1 + l) * 131072),
            conv_b1 + l * HH, nullptr, g_t, NN);
        k_mma<false, false><<<dim3(mb, 2), 256, SMEM_BYTES>>>(
            g_t, nullptr, (const __half*)(g_wsp + (size_t)(4 + l) * 131072),
            conv_b2 + l * HH, nullptr, g_h, NN);
        // GraphNorm: one pass for sum + sumsq, finalize, normalize
        k_zero_f<<<(GG * HH + 255) / 256, 256>>>(g_gsum, GG * HH);
        k_zero_f<<<(GG * HH + 255) / 256, 256>>>(g_gsumsq, GG * HH);
        k_seg2<true><<<(NN + 15) / 16, 256>>>(g_h, g_gsum, g_gsumsq, batch);
        k_fin2<<<(GG * HH + 255) / 256, 256>>>(norm_alpha + l * HH);
        k_norm<<<(NN * 32 + 255) / 256, 256>>>(batch, norm_gamma, norm_beta, norm_alpha, l);
    }

    // 6. mean pool + head
    k_zero_f<<<(GG * HH + 255) / 256, 256>>>(g_gsum, GG * HH);
    k_seg2<false><<<(NN + 15) / 16, 256>>>(g_h, g_gsum, nullptr, batch);
    k_finpool<<<(GG * HH + 255) / 256, 256>>>();
    k_head<<<GG, 256>>>(head_W1, head_W2, head_b2, out);
}

// round 8
// speedup vs baseline: 3.0936x; 1.0192x over previous
#include <cuda_runtime.h>
#include <cuda_fp16.h>
#include <cstdint>

#define NN 100000
#define EE 400000
#define GG 256
#define HH 256
#define BIOD 512
#define GEPS 1e-5f

// ---------------- scratch (device globals) ----------------
static __device__ __half d_h[(size_t)NN * HH];
static __device__ __half d_z[(size_t)NN * HH];
static __device__ __half d_e[(size_t)EE * HH];   // stored in CSR-slot order
static __device__ int    d_deg[NN];
static __device__ int    d_rowptr[NN + 1];
static __device__ int    d_cursor[NN];
static __device__ int    d_epos[EE];             // edge id -> CSR slot
static __device__ int    d_srcv[EE];             // CSR slot -> src node
static __device__ float  d_Wc[4 * HH];
static __device__ float  d_bc[HH];
static __device__ float  d_biob[HH];
static __device__ float  d_gsum[GG * HH];
static __device__ float  d_gsumsq[GG * HH];
static __device__ float  d_gvar[GG * HH];
static __device__ float  d_gmean[GG * HH];
static __device__ float  d_gcnt[GG];
static __device__ float  d_gpool[GG * HH];
// 7 weight matrices x 256x256 fp16, layout [mat][n][k], stride 131072
static __device__ unsigned short d_wsplit[(size_t)7 * 2 * 65536];

// ---------------- asm helpers ----------------
__device__ __forceinline__ uint32_t smem_to_u32(const void* smem_ptr) {
    uint32_t addr;
    asm("{ .reg .u64 tmp; cvta.to.shared.u64 tmp, %1; cvt.u32.u64 %0, tmp; }"
        : "=r"(addr) : "l"(smem_ptr));
    return addr;
}
__device__ __forceinline__ void ldsm4(unsigned* r, uint32_t addr) {
    asm volatile("ldmatrix.sync.aligned.m8n8.x4.shared.b16 {%0,%1,%2,%3}, [%4];"
                 : "=r"(r[0]), "=r"(r[1]), "=r"(r[2]), "=r"(r[3]) : "r"(addr));
}
__device__ __forceinline__ void mma16816(float* d, const unsigned* a, const unsigned* b) {
    asm volatile(
        "mma.sync.aligned.m16n8k16.row.col.f32.f16.f16.f32 "
        "{%0,%1,%2,%3}, {%4,%5,%6,%7}, {%8,%9}, {%0,%1,%2,%3};"
        : "+f"(d[0]), "+f"(d[1]), "+f"(d[2]), "+f"(d[3])
        : "r"(a[0]), "r"(a[1]), "r"(a[2]), "r"(a[3]), "r"(b[0]), "r"(b[1]));
}
__device__ __forceinline__ void cpasync16(uint32_t dst, const void* src) {
    asm volatile("cp.async.ca.shared.global [%0], [%1], 16;" :: "r"(dst), "l"(src));
}
#define CP_COMMIT() asm volatile("cp.async.commit_group;" ::: "memory")
#define CP_WAIT(n)  asm volatile("cp.async.wait_group %0;" :: "n"(n) : "memory")

__device__ __forceinline__ unsigned pack2(float a, float b) {
    __half2 h = __floats2half2_rn(a, b);
    return *(unsigned*)&h;
}

#define PITCH 72
#define BUFH 9216                          // halves per stage buffer
#define PITCH_T 264                        // t-tile pitch (ldmatrix conflict-free)

// shared 4-kstep compute: A at (abase, apitch, col offset acol0), B at (bbase, PITCH)
__device__ __forceinline__ void compute_chunk(
    float acc[4][4][4], uint32_t abase, int apitch, int acol0,
    uint32_t bbase, int lane, int wm, int wn) {
#pragma unroll
    for (int ks = 0; ks < 64; ks += 16) {
        unsigned fA[4][4];
#pragma unroll
        for (int mt = 0; mt < 4; mt++) {
            int mrow = wm * 64 + mt * 16 + (lane & 15);
            ldsm4(fA[mt], abase + (uint32_t)(mrow * apitch + acol0 + ks + ((lane >> 4) << 3)) * 2);
        }
#pragma unroll
        for (int p = 0; p < 2; p++) {
            int g = lane >> 3, j = lane & 7;
            int nrow = wn * 32 + p * 16 + (g >> 1) * 8 + j;
            int kk = ks + (g & 1) * 8;
            unsigned fB[4];
            ldsm4(fB, bbase + (uint32_t)(nrow * PITCH + kk) * 2);
#pragma unroll
            for (int mt = 0; mt < 4; mt++) {
                mma16816(acc[mt][2 * p], fA[mt], fB);
                mma16816(acc[mt][2 * p + 1], fA[mt], fB + 2);
            }
        }
    }
}

// ============================================================================
// Edge GEMM (AF): e_row = (relu(attr@Wc+bc) @ W2 + b2) * struct, stored to
// CSR slot epos[row].  Double-buffered cp.async for B; A computed in regs.
// ============================================================================
#define EMMA_SMEM (4 * BUFH * 2 + 2048)

__global__ __launch_bounds__(256, 2) void k_emma(
    const float* __restrict__ attr, const __half* __restrict__ W,
    const float* __restrict__ bias, const float* __restrict__ sscale,
    __half* __restrict__ C) {
    extern __shared__ __half smh[];
    const uint32_t sbase = smem_to_u32(smh);
    float* sattr = (float*)(smh + 4 * BUFH);

    int tid = threadIdx.x, lane = tid & 31, wid = tid >> 5;
    int wm = wid >> 2, wn = wid & 3;
    int row0 = blockIdx.x * 128;
    int n0 = blockIdx.y * 128;

    if (tid < 128)
        *(float4*)(sattr + tid * 4) = *(const float4*)(attr + (size_t)(row0 + tid) * 4);
    __syncthreads();

    float acc[4][4][4];
#pragma unroll
    for (int mt = 0; mt < 4; mt++)
#pragma unroll
        for (int nt = 0; nt < 4; nt++)
#pragma unroll
            for (int j = 0; j < 4; j++) acc[mt][nt][j] = 0.f;

    const int hr = tid >> 1, kh = (tid & 1) * 32;
    const int kp = tid >> 3, rg = tid & 7;

    auto stage = [&](int c, int buf) {
        int k0 = c * 64;
        {
            const __half* pb = W + (size_t)(n0 + hr) * 256 + k0 + kh;
            uint32_t db = sbase + (uint32_t)(2 * BUFH + buf * BUFH + hr * PITCH + kh) * 2;
#pragma unroll
            for (int q = 0; q < 4; q++) cpasync16(db + q * 16, pb + q * 8);
        }
        {
            int k = k0 + 2 * kp;
            float2 w0 = *(const float2*)(d_Wc + k);
            float2 w1 = *(const float2*)(d_Wc + 256 + k);
            float2 w2 = *(const float2*)(d_Wc + 512 + k);
            float2 w3 = *(const float2*)(d_Wc + 768 + k);
            float2 bb = *(const float2*)(d_bc + k);
            __half* sA = smh + buf * BUFH;
#pragma unroll
            for (int i = 0; i < 16; i++) {
                int r = rg + 8 * i;
                float4 a = *(const float4*)(sattr + r * 4);
                float v0 = fmaxf(a.x * w0.x + a.y * w1.x + a.z * w2.x + a.w * w3.x + bb.x, 0.f);
                float v1 = fmaxf(a.x * w0.y + a.y * w1.y + a.z * w2.y + a.w * w3.y + bb.y, 0.f);
                *(unsigned*)&sA[r * PITCH + 2 * kp] = pack2(v0, v1);
            }
        }
    };

    stage(0, 0);
    CP_COMMIT();
#pragma unroll
    for (int c = 0; c < 4; c++) {
        int buf = c & 1;
        __syncthreads();
        if (c < 3) {
            stage(c + 1, buf ^ 1);
            CP_COMMIT();
            CP_WAIT(1);
        } else {
            CP_WAIT(0);
        }
        __syncthreads();
        compute_chunk(acc, sbase + (uint32_t)(buf * BUFH) * 2, PITCH, 0,
                      sbase + (uint32_t)(2 * BUFH + buf * BUFH) * 2, lane, wm, wn);
    }

#pragma unroll
    for (int mt = 0; mt < 4; mt++) {
        int lr1 = wm * 64 + mt * 16 + (lane >> 2);
        int lr2 = lr1 + 8;
        int r1 = row0 + lr1, r2 = row0 + lr2;
        float ssv = __ldg(sscale);
        float s1 = (sattr[lr1 * 4 + 1] > 0.f) ? ssv : 1.f;
        float s2 = (sattr[lr2 * 4 + 1] > 0.f) ? ssv : 1.f;
        size_t o1 = (size_t)d_epos[r1] * HH;
        size_t o2 = (size_t)d_epos[r2] * HH;
#pragma unroll
        for (int nt = 0; nt < 4; nt++) {
            int col = n0 + wn * 32 + nt * 8 + 2 * (lane & 3);
            float2 b = *(const float2*)(bias + col);
            float v0 = (acc[mt][nt][0] + b.x) * s1, v1 = (acc[mt][nt][1] + b.y) * s1;
            float v2 = (acc[mt][nt][2] + b.x) * s2, v3 = (acc[mt][nt][3] + b.y) * s2;
            *(__half2*)(C + o1 + col) = __floats2half2_rn(v0, v1);
            *(__half2*)(C + o2 + col) = __floats2half2_rn(v2, v3);
        }
    }
}

// ============================================================================
// Fused conv layer: h = relu(z@W1+b1)@W2 + b2  (t kept in SMEM)
// ============================================================================
#define CONV_SMEM ((2 * BUFH + 128 * PITCH_T) * 2)   // 104448

__global__ __launch_bounds__(256, 2) void k_conv(
    const __half* __restrict__ Z, const __half* __restrict__ W1h,
    const __half* __restrict__ W2h, const float* __restrict__ bias1,
    const float* __restrict__ bias2, __half* __restrict__ H, int M) {
    extern __shared__ __half smh[];
    const uint32_t sbase = smem_to_u32(smh);
    const uint32_t bufA = sbase;                         // stage buf 0
    const uint32_t bufB = sbase + (uint32_t)BUFH * 2;    // stage buf 1
    __half* sT = smh + 2 * BUFH;
    const uint32_t tbase = sbase + (uint32_t)(2 * BUFH) * 2;

    int tid = threadIdx.x, lane = tid & 31, wid = tid >> 5;
    int wm = wid >> 2, wn = wid & 3;
    int row0 = blockIdx.x * 128;
    const int hr = tid >> 1, kh = (tid & 1) * 32;

    // ---------- GEMM1: t = relu(z@W1+b1) -> sT ----------
    for (int half = 0; half < 2; half++) {
        float acc[4][4][4];
#pragma unroll
        for (int mt = 0; mt < 4; mt++)
#pragma unroll
            for (int nt = 0; nt < 4; nt++)
#pragma unroll
                for (int j = 0; j < 4; j++) acc[mt][nt][j] = 0.f;

        for (int c = 0; c < 4; c++) {
            int k0 = c * 64;
            {
                int rc = min(row0 + hr, M - 1);
                const __half* Ar = Z + (size_t)rc * HH + k0 + kh;
                uint32_t da = bufA + (uint32_t)(hr * PITCH + kh) * 2;
#pragma unroll
                for (int q = 0; q < 4; q++) cpasync16(da + q * 16, Ar + q * 8);
                const __half* Br = W1h + (size_t)(half * 128 + hr) * 256 + k0 + kh;
                uint32_t db = bufB + (uint32_t)(hr * PITCH + kh) * 2;
#pragma unroll
                for (int q = 0; q < 4; q++) cpasync16(db + q * 16, Br + q * 8);
            }
            CP_COMMIT();
            CP_WAIT(0);
            __syncthreads();
            compute_chunk(acc, bufA, PITCH, 0, bufB, lane, wm, wn);
            __syncthreads();
        }
        // epilogue -> sT (relu + bias1)
#pragma unroll
        for (int mt = 0; mt < 4; mt++) {
            int lr1 = wm * 64 + mt * 16 + (lane >> 2);
            int lr2 = lr1 + 8;
#pragma unroll
            for (int nt = 0; nt < 4; nt++) {
                int col = half * 128 + wn * 32 + nt * 8 + 2 * (lane & 3);
                float2 b = *(const float2*)(bias1 + col);
                float v0 = fmaxf(acc[mt][nt][0] + b.x, 0.f);
                float v1 = fmaxf(acc[mt][nt][1] + b.y, 0.f);
                float v2 = fmaxf(acc[mt][nt][2] + b.x, 0.f);
                float v3 = fmaxf(acc[mt][nt][3] + b.y, 0.f);
                *(unsigned*)&sT[lr1 * PITCH_T + col] = pack2(v0, v1);
                *(unsigned*)&sT[lr2 * PITCH_T + col] = pack2(v2, v3);
            }
        }
    }
    __syncthreads();

    // ---------- GEMM2: h = t@W2 + b2 (A from sT; B double-buffered) ----------
    for (int half = 0; half < 2; half++) {
        float acc[4][4][4];
#pragma unroll
        for (int mt = 0; mt < 4; mt++)
#pragma unroll
            for (int nt = 0; nt < 4; nt++)
#pragma unroll
                for (int j = 0; j < 4; j++) acc[mt][nt][j] = 0.f;

        auto stageB = [&](int c, uint32_t buf) {
            const __half* Br = W2h + (size_t)(half * 128 + hr) * 256 + c * 64 + kh;
            uint32_t db = buf + (uint32_t)(hr * PITCH + kh) * 2;
#pragma unroll
            for (int q = 0; q < 4; q++) cpasync16(db + q * 16, Br + q * 8);
        };

        stageB(0, bufA);
        CP_COMMIT();
#pragma unroll
        for (int c = 0; c < 4; c++) {
            uint32_t cur = (c & 1) ? bufB : bufA;
            if (c < 3) {
                stageB(c + 1, (c & 1) ? bufA : bufB);
                CP_COMMIT();
                CP_WAIT(1);
            } else {
                CP_WAIT(0);
            }
            __syncthreads();
            compute_chunk(acc, tbase, PITCH_T, c * 64, cur, lane, wm, wn);
            __syncthreads();
        }
        // epilogue -> H (bias2)
#pragma unroll
        for (int mt = 0; mt < 4; mt++) {
            int r1 = row0 + wm * 64 + mt * 16 + (lane >> 2);
            int r2 = r1 + 8;
#pragma unroll
            for (int nt = 0; nt < 4; nt++) {
                int col = half * 128 + wn * 32 + nt * 8 + 2 * (lane & 3);
                float2 b = *(const float2*)(bias2 + col);
                float v0 = acc[mt][nt][0] + b.x, v1 = acc[mt][nt][1] + b.y;
                float v2 = acc[mt][nt][2] + b.x, v3 = acc[mt][nt][3] + b.y;
                if (r1 < M) *(__half2*)(H + (size_t)r1 * HH + col) = __floats2half2_rn(v0, v1);
                if (r2 < M) *(__half2*)(H + (size_t)r2 * HH + col) = __floats2half2_rn(v2, v3);
            }
        }
    }
}

// ---------------- weight transpose: W[k][n] fp32 -> W[n][k] fp16 ----
__global__ void k_wsplit(const float* __restrict__ eW2, const float* __restrict__ cW1,
                         const float* __restrict__ cW2) {
    int m = blockIdx.x >> 8;
    int n = blockIdx.x & 255;
    const float* W = (m == 0) ? eW2
                   : (m <= 3 ? cW1 + (size_t)(m - 1) * 65536 : cW2 + (size_t)(m - 4) * 65536);
    unsigned short* hi = d_wsplit + (size_t)m * 131072 + n * 256;
    for (int k = threadIdx.x; k < 256; k += 64)
        hi[k] = __half_as_ushort(__float2half_rn(W[(size_t)k * 256 + n]));
}

// ---------------- small helpers ----------------
__global__ void k_zero_i(int* p, int n) {
    int i = blockIdx.x * blockDim.x + threadIdx.x;
    if (i < n) p[i] = 0;
}
__global__ void k_zero2(float* a, float* b, int n) {
    int i = blockIdx.x * blockDim.x + threadIdx.x;
    if (i < n) { a[i] = 0.f; b[i] = 0.f; }
}
__global__ void k_zero_f(float* p, int n) {
    int i = blockIdx.x * blockDim.x + threadIdx.x;
    if (i < n) p[i] = 0.f;
}

__global__ void k_prep(const float* __restrict__ Wemb, const float* __restrict__ eb,
                       const float* __restrict__ W1, const float* __restrict__ b1,
                       const float* __restrict__ bio, const float* __restrict__ hW1,
                       const float* __restrict__ hb1) {
    int j = threadIdx.x;
    float wc0 = 0.f, wc1 = 0.f, wc2 = 0.f, wc3 = 0.f, bc = 0.f;
    for (int d = 0; d < HH; d++) {
        float w = W1[d * HH + j];
        wc0 += Wemb[0 * HH + d] * w;
        wc1 += Wemb[1 * HH + d] * w;
        wc2 += Wemb[2 * HH + d] * w;
        wc3 += Wemb[3 * HH + d] * w;
        bc  += eb[d] * w;
    }
    d_Wc[0 * HH + j] = wc0;
    d_Wc[1 * HH + j] = wc1;
    d_Wc[2 * HH + j] = wc2;
    d_Wc[3 * HH + j] = wc3;
    d_bc[j] = bc + b1[j];
    float bb = hb1[j];
    for (int k = 0; k < BIOD; k++) bb += bio[k] * hW1[(HH + k) * HH + j];
    d_biob[j] = bb;
}

// h[n] = node_emb_W[x[n]]  (fp16 out)
__global__ void k_node_emb(const int* __restrict__ x, const float* __restrict__ emb) {
    int idx = blockIdx.x * blockDim.x + threadIdx.x;
    int node = idx >> 5;
    int q = idx & 31;
    if (node >= NN) return;
    int xv = x[node];
    const float* src = emb + (size_t)xv * HH + q * 8;
    float4 a = *(const float4*)src;
    float4 b = *(const float4*)(src + 4);
    uint4 o;
    o.x = pack2(a.x, a.y); o.y = pack2(a.z, a.w);
    o.z = pack2(b.x, b.y); o.w = pack2(b.z, b.w);
    *(uint4*)(d_h + (size_t)node * HH + q * 8) = o;
}

// ---------------- CSR build over dst ----------------
__global__ void k_deg(const int* __restrict__ ei) {
    int e = blockIdx.x * blockDim.x + threadIdx.x;
    if (e < EE) atomicAdd(&d_deg[ei[EE + e]], 1);
}
__global__ void k_scan() {
    __shared__ int s[1024];
    int tid = threadIdx.x;
    const int chunk = (NN + 1023) / 1024;
    int beg = tid * chunk;
    int end = min(beg + chunk, NN);
    int sum = 0;
    for (int i = beg; i < end; i++) sum += d_deg[i];
    s[tid] = sum;
    __syncthreads();
    for (int off = 1; off < 1024; off <<= 1) {
        int v = (tid >= off) ? s[tid - off] : 0;
        __syncthreads();
        s[tid] += v;
        __syncthreads();
    }
    int run = (tid > 0) ? s[tid - 1] : 0;
    for (int i = beg; i < end; i++) {
        d_rowptr[i] = run;
        d_cursor[i] = run;
        run += d_deg[i];
    }
    if (tid == 1023) d_rowptr[NN] = s[1023];
}
__global__ void k_fill(const int* __restrict__ ei) {
    int e = blockIdx.x * blockDim.x + threadIdx.x;
    if (e < EE) {
        int dst = ei[EE + e];
        int p = atomicAdd(&d_cursor[dst], 1);
        d_epos[e] = p;
        d_srcv[p] = ei[e];
    }
}
__global__ void k_cnt(const int* __restrict__ batch) {
    int i = blockIdx.x * blockDim.x + threadIdx.x;
    if (i < NN) atomicAdd(&d_gcnt[batch[i]], 1.f);
}

// z = (1+eps_l)*h + sum_p relu(h[srcv[p]] + e[p]); e slot-ordered (sequential)
__global__ void k_aggregate(const float* __restrict__ conv_eps, int l) {
    int tid = threadIdx.x;
    int node = blockIdx.x * 8 + (tid >> 5);
    int q = tid & 31;
    if (node >= NN) return;
    float eps1 = 1.f + conv_eps[l];
    float acc[8];
#pragma unroll
    for (int j = 0; j < 8; j++) acc[j] = 0.f;
    int pbeg = d_rowptr[node];
    int pend = d_rowptr[node + 1];
    int p = pbeg;
    for (; p + 1 < pend; p += 2) {
        int s0 = d_srcv[p], s1 = d_srcv[p + 1];
        uint4 h0 = *(const uint4*)(d_h + (size_t)s0 * HH + q * 8);
        uint4 e0 = *(const uint4*)(d_e + (size_t)p * HH + q * 8);
        uint4 h1 = *(const uint4*)(d_h + (size_t)s1 * HH + q * 8);
        uint4 e1 = *(const uint4*)(d_e + (size_t)(p + 1) * HH + q * 8);
        const unsigned *hw0 = &h0.x, *ew0 = &e0.x, *hw1 = &h1.x, *ew1 = &e1.x;
#pragma unroll
        for (int j = 0; j < 4; j++) {
            float2 a = __half22float2(*(const __half2*)&hw0[j]);
            float2 b = __half22float2(*(const __half2*)&ew0[j]);
            float2 c = __half22float2(*(const __half2*)&hw1[j]);
            float2 d = __half22float2(*(const __half2*)&ew1[j]);
            acc[2 * j]     += fmaxf(a.x + b.x, 0.f) + fmaxf(c.x + d.x, 0.f);
            acc[2 * j + 1] += fmaxf(a.y + b.y, 0.f) + fmaxf(c.y + d.y, 0.f);
        }
    }
    if (p < pend) {
        int s0 = d_srcv[p];
        uint4 h0 = *(const uint4*)(d_h + (size_t)s0 * HH + q * 8);
        uint4 e0 = *(const uint4*)(d_e + (size_t)p * HH + q * 8);
        const unsigned *hw0 = &h0.x, *ew0 = &e0.x;
#pragma unroll
        for (int j = 0; j < 4; j++) {
            float2 a = __half22float2(*(const __half2*)&hw0[j]);
            float2 b = __half22float2(*(const __half2*)&ew0[j]);
            acc[2 * j]     += fmaxf(a.x + b.x, 0.f);
            acc[2 * j + 1] += fmaxf(a.y + b.y, 0.f);
        }
    }
    uint4 hs = *(const uint4*)(d_h + (size_t)node * HH + q * 8);
    const unsigned* hw = &hs.x;
    uint4 o;
    unsigned* ow = &o.x;
#pragma unroll
    for (int j = 0; j < 4; j++) {
        float2 hf = __half22float2(*(const __half2*)&hw[j]);
        ow[j] = pack2(eps1 * hf.x + acc[2 * j], eps1 * hf.y + acc[2 * j + 1]);
    }
    *(uint4*)(d_z + (size_t)node * HH + q * 8) = o;
}

// fused segment sum + sum of squares over sorted batch
__global__ void k_seg2(const __half* __restrict__ src, const int* __restrict__ batch) {
    int n0 = blockIdx.x * 16;
    int d = threadIdx.x;
    float a1 = 0.f, a2 = 0.f;
    int cur = -1;
#pragma unroll 4
    for (int i = 0; i < 16; i++) {
        int node = n0 + i;
        if (node >= NN) break;
        int g = batch[node];
        if (g != cur) {
            if (cur >= 0) {
                atomicAdd(&d_gsum[cur * HH + d], a1);
                atomicAdd(&d_gsumsq[cur * HH + d], a2);
            }
            cur = g;
            a1 = 0.f; a2 = 0.f;
        }
        float v = __half2float(src[(size_t)node * HH + d]);
        a1 += v;
        a2 += v * v;
    }
    if (cur >= 0) {
        atomicAdd(&d_gsum[cur * HH + d], a1);
        atomicAdd(&d_gsumsq[cur * HH + d], a2);
    }
}

// finalize mean + variance; if gamma_l != null also emit gpool directly:
//   mean(norm(h)) over graph = gamma*(1-alpha)*mean*rsqrt(var+eps)+beta
__global__ void k_fin2(const float* __restrict__ alpha_l,
                       const float* __restrict__ gamma_l,
                       const float* __restrict__ beta_l) {
    int i = blockIdx.x * blockDim.x + threadIdx.x;
    if (i >= GG * HH) return;
    float n = fmaxf(d_gcnt[i >> 8], 1.f);
    float m = d_gsum[i] / n;
    d_gmean[i] = m;
    int d = i & 255;
    float a = alpha_l[d];
    float var = d_gsumsq[i] / n - a * (2.f - a) * m * m;
    d_gvar[i] = var;
    if (gamma_l) {
        d_gpool[i] = gamma_l[d] * (1.f - a) * m * rsqrtf(var + GEPS) + beta_l[d];
    }
}

// h = gamma*(h - alpha*mean)*rsqrt(var+eps) + beta   (fp16 in/out)
__global__ void k_norm(const int* __restrict__ batch, const float* __restrict__ gamma,
                       const float* __restrict__ beta, const float* __restrict__ alpha, int l) {
    int idx = blockIdx.x * blockDim.x + threadIdx.x;
    int node = idx >> 5;
    int q = idx & 31;
    if (node >= NN) return;
    int g = batch[node];
    uint4 hv = *(const uint4*)(d_h + (size_t)node * HH + q * 8);
    const unsigned* hw = &hv.x;
    uint4 o;
    unsigned* ow = &o.x;
#pragma unroll
    for (int j = 0; j < 4; j++) {
        int ch = q * 8 + 2 * j;
        float2 hf = __half22float2(*(const __half2*)&hw[j]);
        float2 m = *(const float2*)(d_gmean + g * HH + ch);
        float2 v = *(const float2*)(d_gvar + g * HH + ch);
        float2 ga = *(const float2*)(gamma + l * HH + ch);
        float2 be = *(const float2*)(beta + l * HH + ch);
        float2 al = *(const float2*)(alpha + l * HH + ch);
        float o0 = ga.x * (hf.x - al.x * m.x) * rsqrtf(v.x + GEPS) + be.x;
        float o1 = ga.y * (hf.y - al.y * m.y) * rsqrtf(v.y + GEPS) + be.y;
        ow[j] = pack2(o0, o1);
    }
    *(uint4*)(d_h + (size_t)node * HH + q * 8) = o;
}

__global__ void k_head(const float* __restrict__ hW1, const float* __restrict__ hW2,
                       const float* __restrict__ hb2, float* __restrict__ out) {
    int g = blockIdx.x;
    int j = threadIdx.x;
    __shared__ float red[256];
    float acc = d_biob[j];
    const float* grow = d_gpool + g * HH;
    for (int k = 0; k < HH; k++) acc += grow[k] * hW1[k * HH + j];
    red[j] = fmaxf(acc, 0.f) * hW2[j];
    __syncthreads();
    for (int off = 128; off > 0; off >>= 1) {
        if (j < off) red[j] += red[j + off];
        __syncthreads();
    }
    if (j == 0) out[g] = red[0] + hb2[0];
}

// ---------------- launch ----------------
extern "C" void kernel_launch(void* const* d_in, const int* in_sizes, int n_in,
                              void* d_out, int out_size) {
    const int* x = (const int*)d_in[0];
    const int* ei = (const int*)d_in[1];
    const float* edge_attr = (const float*)d_in[2];
    const int* batch = (const int*)d_in[3];
    const float* node_emb_W = (const float*)d_in[4];
    const float* edge_emb_W = (const float*)d_in[5];
    const float* edge_emb_b = (const float*)d_in[6];
    const float* edge_mlp_W1 = (const float*)d_in[7];
    const float* edge_mlp_b1 = (const float*)d_in[8];
    const float* edge_mlp_W2 = (const float*)d_in[9];
    const float* edge_mlp_b2 = (const float*)d_in[10];
    const float* struct_scale = (const float*)d_in[11];
    const float* conv_W1 = (const float*)d_in[12];
    const float* conv_b1 = (const float*)d_in[13];
    const float* conv_W2 = (const float*)d_in[14];
    const float* conv_b2 = (const float*)d_in[15];
    const float* conv_eps = (const float*)d_in[16];
    const float* norm_gamma = (const float*)d_in[17];
    const float* norm_beta = (const float*)d_in[18];
    const float* norm_alpha = (const float*)d_in[19];
    const float* mean_bio = (const float*)d_in[20];
    const float* head_W1 = (const float*)d_in[21];
    const float* head_b1 = (const float*)d_in[22];
    const float* head_W2 = (const float*)d_in[23];
    const float* head_b2 = (const float*)d_in[24];
    float* out = (float*)d_out;
    (void)in_sizes; (void)n_in; (void)out_size;

    float *g_gsum, *g_gsumsq, *g_gcnt;
    __half *g_e, *g_z, *g_h;
    int* g_deg;
    unsigned short* g_wsp;
    cudaGetSymbolAddress((void**)&g_gsum, d_gsum);
    cudaGetSymbolAddress((void**)&g_gsumsq, d_gsumsq);
    cudaGetSymbolAddress((void**)&g_gcnt, d_gcnt);
    cudaGetSymbolAddress((void**)&g_e, d_e);
    cudaGetSymbolAddress((void**)&g_z, d_z);
    cudaGetSymbolAddress((void**)&g_h, d_h);
    cudaGetSymbolAddress((void**)&g_deg, d_deg);
    cudaGetSymbolAddress((void**)&g_wsp, d_wsplit);

    cudaFuncSetAttribute(k_emma, cudaFuncAttributeMaxDynamicSharedMemorySize, EMMA_SMEM);
    cudaFuncSetAttribute(k_conv, cudaFuncAttributeMaxDynamicSharedMemorySize, CONV_SMEM);

    // 1. fold small weights; transpose big weights to fp16 [n][k]
    k_prep<<<1, 256>>>(edge_emb_W, edge_emb_b, edge_mlp_W1, edge_mlp_b1,
                       mean_bio, head_W1, head_b1);
    k_wsplit<<<7 * 256, 64>>>(edge_mlp_W2, conv_W1, conv_W2);
    // 2. node embedding (fp16)
    k_node_emb<<<(NN * 32 + 255) / 256, 256>>>(x, node_emb_W);
    // 3. CSR build (before edge GEMM: epos needed for permuted store)
    k_zero_i<<<(NN + 255) / 256, 256>>>(g_deg, NN);
    k_deg<<<(EE + 255) / 256, 256>>>(ei);
    k_scan<<<1, 1024>>>();
    k_fill<<<(EE + 255) / 256, 256>>>(ei);
    // 4. edge features -> CSR slots
    k_emma<<<dim3(EE / 128, 2), 256, EMMA_SMEM>>>(
        edge_attr, (const __half*)g_wsp, edge_mlp_b2, struct_scale, g_e);
    // 5. per-graph counts
    k_zero_f<<<1, 256>>>(g_gcnt, GG);
    k_cnt<<<(NN + 255) / 256, 256>>>(batch);

    const int mb = (NN + 127) / 128;
    for (int l = 0; l < 3; l++) {
        k_aggregate<<<(NN + 7) / 8, 256>>>(conv_eps, l);
        k_conv<<<mb, 256, CONV_SMEM>>>(
            g_z, (const __half*)(g_wsp + (size_t)(1 + l) * 131072),
            (const __half*)(g_wsp + (size_t)(4 + l) * 131072),
            conv_b1 + l * HH, conv_b2 + l * HH, g_h, NN);
        k_zero2<<<(GG * HH + 255) / 256, 256>>>(g_gsum, g_gsumsq, GG * HH);
        k_seg2<<<(NN + 15) / 16, 256>>>(g_h, batch);
        k_fin2<<<(GG * HH + 255) / 256, 256>>>(
            norm_alpha + l * HH,
            (l == 2) ? (norm_gamma + l * HH) : nullptr,
            (l == 2) ? (norm_beta + l * HH) : nullptr);
        if (l < 2)
            k_norm<<<(NN * 32 + 255) / 256, 256>>>(batch, norm_gamma, norm_beta, norm_alpha, l);
    }

    // 6. head (gpool already produced by k_fin2 at l==2)
    k_head<<<GG, 256>>>(head_W1, head_W2, head_b2, out);
}